// round 7
// baseline (speedup 1.0000x reference)
#include <cuda_runtime.h>
#include <cuda_bf16.h>
#include <cstdint>
#include <math.h>

#define T_TOK 2176
#define HS    2048
#define NQKV  3072
#define NH    16
#define NKV   4
#define HD    128
#define MMETA 128
#define WWIN  512
#define SCALE_F 0.08838834764831845f
#define NEGV  -1.0e30f

// ---------------------------------------------------------------------------
// scratch buffers
// ---------------------------------------------------------------------------
__device__ float g_qkv[T_TOK * NQKV];                    // Q roped+scaled fp32
__device__ __nv_bfloat16 g_Ahi[T_TOK * HS];
__device__ __nv_bfloat16 g_Alo[T_TOK * HS];
__device__ __nv_bfloat16 g_Bthi[NQKV * HS];              // W transposed [n][k]
__device__ __nv_bfloat16 g_Btlo[NQKV * HS];
__device__ __nv_bfloat16 g_Khi[T_TOK * NKV * HD];
__device__ __nv_bfloat16 g_Klo[T_TOK * NKV * HD];
__device__ __nv_bfloat16 g_Vhi[T_TOK * NKV * HD];
__device__ __nv_bfloat16 g_Vlo[T_TOK * NKV * HD];
__device__ float g_invfreq[64];

__device__ __forceinline__ uint32_t smem_to_u32(const void* p) {
    uint32_t a;
    asm("{ .reg .u64 t; cvta.to.shared.u64 t, %1; cvt.u32.u64 %0, t; }" : "=r"(a) : "l"(p));
    return a;
}
__device__ __forceinline__ uint32_t cvt_bf16x2(float hi, float lo) {
    uint32_t d;
    asm("cvt.rn.bf16x2.f32 %0, %1, %2;" : "=r"(d) : "f"(hi), "f"(lo));
    return d;
}
__device__ __forceinline__ void ldsm_x4(uint32_t* r, uint32_t addr) {
    asm volatile("ldmatrix.sync.aligned.m8n8.x4.shared.b16 {%0,%1,%2,%3}, [%4];"
                 : "=r"(r[0]), "=r"(r[1]), "=r"(r[2]), "=r"(r[3]) : "r"(addr));
}
__device__ __forceinline__ void ldsm_x4t(uint32_t* r, uint32_t addr) {
    asm volatile("ldmatrix.sync.aligned.m8n8.x4.trans.shared.b16 {%0,%1,%2,%3}, [%4];"
                 : "=r"(r[0]), "=r"(r[1]), "=r"(r[2]), "=r"(r[3]) : "r"(addr));
}
__device__ __forceinline__ void mma_bf16(float* c, const uint32_t* a, const uint32_t* b) {
    asm volatile(
        "mma.sync.aligned.m16n8k16.row.col.f32.bf16.bf16.f32 "
        "{%0,%1,%2,%3}, {%4,%5,%6,%7}, {%8,%9}, {%0,%1,%2,%3};"
        : "+f"(c[0]), "+f"(c[1]), "+f"(c[2]), "+f"(c[3])
        : "r"(a[0]), "r"(a[1]), "r"(a[2]), "r"(a[3]), "r"(b[0]), "r"(b[1]));
}
__device__ __forceinline__ void cp_async16(uint32_t dst, const void* src) {
    asm volatile("cp.async.ca.shared.global [%0], [%1], 16;" :: "r"(dst), "l"(src) : "memory");
}
#define CP_COMMIT() asm volatile("cp.async.commit_group;" ::: "memory")
#define CP_WAIT1()  asm volatile("cp.async.wait_group 1;" ::: "memory")
#define CP_WAIT0()  asm volatile("cp.async.wait_group 0;" ::: "memory")

// ---------------------------------------------------------------------------
__global__ void init_invfreq_kernel() {
    int i = threadIdx.x;
    g_invfreq[i] = (float)exp(-(double)(2 * i) * (1.0 / 128.0) * log(10000.0));
}

__global__ void split_a_kernel(const float* __restrict__ A) {
    int i = (blockIdx.x * blockDim.x + threadIdx.x) * 4;
    if (i >= T_TOK * HS) return;
    float4 v = *(const float4*)&A[i];
    __nv_bfloat16 h0 = __float2bfloat16(v.x);
    __nv_bfloat16 h1 = __float2bfloat16(v.y);
    __nv_bfloat16 h2 = __float2bfloat16(v.z);
    __nv_bfloat16 h3 = __float2bfloat16(v.w);
    __nv_bfloat162 hi01, hi23, lo01, lo23;
    hi01.x = h0; hi01.y = h1; hi23.x = h2; hi23.y = h3;
    lo01.x = __float2bfloat16(v.x - __bfloat162float(h0));
    lo01.y = __float2bfloat16(v.y - __bfloat162float(h1));
    lo23.x = __float2bfloat16(v.z - __bfloat162float(h2));
    lo23.y = __float2bfloat16(v.w - __bfloat162float(h3));
    *(__nv_bfloat162*)&g_Ahi[i]     = hi01;
    *(__nv_bfloat162*)&g_Ahi[i + 2] = hi23;
    *(__nv_bfloat162*)&g_Alo[i]     = lo01;
    *(__nv_bfloat162*)&g_Alo[i + 2] = lo23;
}

__global__ void split_w_kernel(const float* __restrict__ W) {
    __shared__ float tile[32][33];
    int n0 = blockIdx.x * 32;
    int k0 = blockIdx.y * 32;
    int tx = threadIdx.x;
    int ty = threadIdx.y;
#pragma unroll
    for (int p = 0; p < 4; ++p) {
        int k = ty + p * 8;
        tile[k][tx] = W[(size_t)(k0 + k) * NQKV + n0 + tx];
    }
    __syncthreads();
#pragma unroll
    for (int p = 0; p < 4; ++p) {
        int n = ty + p * 8;
        float v = tile[tx][n];
        __nv_bfloat16 hi = __float2bfloat16(v);
        __nv_bfloat16 lo = __float2bfloat16(v - __bfloat162float(hi));
        size_t o = (size_t)(n0 + n) * HS + k0 + tx;
        g_Bthi[o] = hi;
        g_Btlo[o] = lo;
    }
}

// ---------------------------------------------------------------------------
// Stage 1: bf16x3 GEMM, CTA 128x128, 8 warps (64x32), BK=32,
// 3-stage cp.async pipeline (occ 1), ONE barrier per chunk.
// Fused epilogue: bias + RoPE + Q-scale + K/V split.
// ---------------------------------------------------------------------------
#define BK 32
#define TILE_B (128 * 80)
#define STAGE_B (4 * TILE_B)          // 40960
#define GEMM_SMEM (3 * STAGE_B)       // 122880

__global__ __launch_bounds__(256, 1)
void qkv_mma_kernel(const float* __restrict__ bias, const int* __restrict__ pos) {
    extern __shared__ char smem[];
    const uint32_t sb = smem_to_u32(smem);
    const int tid  = threadIdx.x;
    const int wid  = tid >> 5;
    const int lane = tid & 31;
    const int head = blockIdx.x;            // 0..23
    const int bm = blockIdx.y * 128;
    const int bn = head * 128;
    const int wm = (wid >> 2) * 64;
    const int wn = (wid & 3) * 32;

    const __nv_bfloat16* srcs[4] = {
        g_Ahi + (size_t)bm * HS, g_Alo + (size_t)bm * HS,
        g_Bthi + (size_t)bn * HS, g_Btlo + (size_t)bn * HS };

    auto issue_stage = [&](int c, int s) {
#pragma unroll
        for (int q = 0; q < 8; ++q) {
            int idx = q * 256 + tid;
            int t   = idx >> 9;
            int cc  = idx & 511;
            int row = cc >> 2;
            int seg = cc & 3;
            const __nv_bfloat16* src = srcs[t] + (size_t)row * HS + c * BK + seg * 8;
            uint32_t dst = sb + s * STAGE_B + t * TILE_B + row * 80 + seg * 16;
            cp_async16(dst, src);
        }
    };

    float acc[4][4][4];
#pragma unroll
    for (int i = 0; i < 4; ++i)
#pragma unroll
        for (int j = 0; j < 4; ++j)
#pragma unroll
            for (int q = 0; q < 4; ++q) acc[i][j][q] = 0.f;

    issue_stage(0, 0); CP_COMMIT();
    issue_stage(1, 1); CP_COMMIT();

    const int arow  = wm + (lane & 15);
    const int acolh = (lane >> 4) << 3;
    const int brow4 = (lane & 7) + ((lane >> 4) & 1) * 8;
    const int bcol4 = ((lane >> 3) & 1) * 8;

    const int NCH = HS / BK;   // 64
    int buf = 0;
    for (int c = 0; c < NCH; ++c) {
        CP_WAIT1();
        __syncthreads();                    // stage c visible; buf (c-1)%3 free

        int nc = c + 2;
        if (nc < NCH) {
            int nb = nc - 3 * (nc / 3 * 0);  // (avoid div) -- compute below
            nb = nc % 3;
            issue_stage(nc, nb);
        }
        CP_COMMIT();

        const uint32_t base = sb + buf * STAGE_B;
#pragma unroll
        for (int ks = 0; ks < 2; ++ks) {
            uint32_t ahi[4][4], alo[4][4];
#pragma unroll
            for (int i = 0; i < 4; ++i) {
                uint32_t aaddr = base + (arow + i * 16) * 80 + (acolh + ks * 16) * 2;
                ldsm_x4(ahi[i], aaddr);
                ldsm_x4(alo[i], aaddr + TILE_B);
            }
#pragma unroll
            for (int jp = 0; jp < 2; ++jp) {
                uint32_t bh[4], bl[4];
                uint32_t baddr = base + 2 * TILE_B +
                                 (wn + jp * 16 + brow4) * 80 + (bcol4 + ks * 16) * 2;
                ldsm_x4(bh, baddr);
                ldsm_x4(bl, baddr + TILE_B);
#pragma unroll
                for (int i = 0; i < 4; ++i) {
                    mma_bf16(acc[i][2 * jp], ahi[i], bh);
                    mma_bf16(acc[i][2 * jp], ahi[i], bl);
                    mma_bf16(acc[i][2 * jp], alo[i], bh);
                    mma_bf16(acc[i][2 * jp + 1], ahi[i], bh + 2);
                    mma_bf16(acc[i][2 * jp + 1], ahi[i], bl + 2);
                    mma_bf16(acc[i][2 * jp + 1], alo[i], bh + 2);
                }
            }
        }
        buf = (buf == 2) ? 0 : buf + 1;
    }

    // ---- fused epilogue ----
    CP_WAIT0();
    __syncthreads();
    float* Ct = (float*)smem;                 // [128][132] fp32 = 67584 B
    const int r  = lane >> 2;
    const int cc = (lane & 3) * 2;
#pragma unroll
    for (int i = 0; i < 4; ++i) {
#pragma unroll
        for (int j = 0; j < 4; ++j) {
            int col = wn + j * 8 + cc;
            float b0 = bias[bn + col], b1 = bias[bn + col + 1];
            int row = wm + i * 16 + r;
            Ct[row * 132 + col]           = acc[i][j][0] + b0;
            Ct[row * 132 + col + 1]       = acc[i][j][1] + b1;
            Ct[(row + 8) * 132 + col]     = acc[i][j][2] + b0;
            Ct[(row + 8) * 132 + col + 1] = acc[i][j][3] + b1;
        }
    }
    __syncthreads();

#pragma unroll 4
    for (int p = 0; p < 32; ++p) {
        int idx = p * 256 + tid;
        int row = idx >> 6;
        int i   = idx & 63;
        int t   = bm + row;
        float x1 = Ct[row * 132 + i];
        float x2 = Ct[row * 132 + i + 64];
        if (head < 20) {
            float ang = (float)pos[t] * g_invfreq[i];
            float c = cosf(ang), s = sinf(ang);
            float y1 = x1 * c - x2 * s;
            float y2 = x2 * c + x1 * s;
            if (head < 16) {
                g_qkv[(size_t)t * NQKV + head * HD + i]      = y1 * SCALE_F;
                g_qkv[(size_t)t * NQKV + head * HD + i + 64] = y2 * SCALE_F;
            } else {
                size_t o = (size_t)t * (NKV * HD) + (head - 16) * HD + i;
                __nv_bfloat16 h1 = __float2bfloat16(y1);
                __nv_bfloat16 h2 = __float2bfloat16(y2);
                g_Khi[o]      = h1;
                g_Khi[o + 64] = h2;
                g_Klo[o]      = __float2bfloat16(y1 - __bfloat162float(h1));
                g_Klo[o + 64] = __float2bfloat16(y2 - __bfloat162float(h2));
            }
        } else {
            size_t o = (size_t)t * (NKV * HD) + (head - 20) * HD + i;
            __nv_bfloat16 h1 = __float2bfloat16(x1);
            __nv_bfloat16 h2 = __float2bfloat16(x2);
            g_Vhi[o]      = h1;
            g_Vhi[o + 64] = h2;
            g_Vlo[o]      = __float2bfloat16(x1 - __bfloat162float(h1));
            g_Vlo[o + 64] = __float2bfloat16(x2 - __bfloat162float(h2));
        }
    }
}

// ---------------------------------------------------------------------------
// Stage 3: attention, 3-stage pipeline, one barrier per k-tile.
// ---------------------------------------------------------------------------
#define APITCH 272
#define ARR_B  (64 * APITCH)
#define ASTAGE (4 * ARR_B)            // 69632
#define ATTN_SMEM (3 * ASTAGE)        // 208896

__global__ __launch_bounds__(256, 1)
void attn_mma_kernel(float* __restrict__ out) {
    extern __shared__ char smc[];
    const uint32_t smu = smem_to_u32(smc);
    const int tid  = threadIdx.x;
    const int wid  = tid >> 5;
    const int lane = tid & 31;

    const int qt   = 33 - blockIdx.x;
    const int hp   = blockIdx.y;
    const int head = hp * 2 + (wid >> 2);
    const int kvh  = hp >> 1;
    const int t0   = qt * 64;
    const int mrow = (wid & 3) * 16;

    const int r  = lane >> 2;
    const int cc = (lane & 3) * 2;

    int kts[12];
    int nkt = 0;
    if (t0 >= MMETA && qt >= 10) {
        kts[nkt++] = 0; kts[nkt++] = 1;
        for (int k = qt - 8; k <= qt; ++k) kts[nkt++] = k;
    } else {
        for (int k = 0; k <= qt; ++k) kts[nkt++] = k;
    }

    uint32_t qhi[8][4], qlo[8][4];
    {
        const float* qb = &g_qkv[(size_t)(t0 + mrow) * NQKV + head * HD];
#pragma unroll
        for (int ks = 0; ks < 8; ++ks) {
#pragma unroll
            for (int rg = 0; rg < 4; ++rg) {
                int row = r + (rg & 1) * 8;
                int col = ks * 16 + cc + (rg >> 1) * 8;
                float2 v = *(const float2*)&qb[(size_t)row * NQKV + col];
                uint32_t h = cvt_bf16x2(v.y, v.x);
                float f0 = __uint_as_float(h << 16);
                float f1 = __uint_as_float(h & 0xffff0000u);
                qhi[ks][rg] = h;
                qlo[ks][rg] = cvt_bf16x2(v.y - f1, v.x - f0);
            }
        }
    }

    const __nv_bfloat16* srcKV[4] = { g_Khi, g_Klo, g_Vhi, g_Vlo };
    auto issue = [&](int ti, int buf) {
        int s0 = kts[ti] * 64;
#pragma unroll
        for (int q = 0; q < 16; ++q) {
            int idx = q * 256 + tid;
            int arr = idx >> 10;
            int rem = idx & 1023;
            int row = rem >> 4;
            int ch  = rem & 15;
            const __nv_bfloat16* src = srcKV[arr] + (size_t)(s0 + row) * (NKV * HD) + kvh * HD + ch * 8;
            uint32_t dst = smu + buf * ASTAGE + arr * ARR_B + row * APITCH + ch * 16;
            cp_async16(dst, src);
        }
    };

    const uint32_t koff = (lane & 7) * APITCH + (lane >> 3) * 16;
    const uint32_t voff = ((lane & 7) + ((lane >> 3) & 1) * 8) * APITCH + ((lane >> 3) >> 1) * 16;

    float oacc[16][4];
#pragma unroll
    for (int j = 0; j < 16; ++j)
#pragma unroll
        for (int q = 0; q < 4; ++q) oacc[j][q] = 0.f;
    float m0 = -3.0e38f, m1 = -3.0e38f, l0 = 0.f, l1 = 0.f;

    const int tr0 = t0 + mrow + r;
    const int tr1 = tr0 + 8;

    issue(0, 0); CP_COMMIT();
    if (nkt > 1) issue(1, 1);
    CP_COMMIT();

    int buf = 0;
    for (int it = 0; it < nkt; ++it) {
        CP_WAIT1();
        __syncthreads();                    // stage it ready; buf (it-1)%3 free

        if (it + 2 < nkt) issue(it + 2, (it + 2) % 3);
        CP_COMMIT();

        const uint32_t kb = smu + buf * ASTAGE;
        const uint32_t vb = kb + 2 * ARR_B;
        const int s0 = kts[it] * 64;

        float sacc[8][4];
#pragma unroll
        for (int j = 0; j < 8; ++j)
#pragma unroll
            for (int q = 0; q < 4; ++q) sacc[j][q] = 0.f;

#pragma unroll
        for (int j = 0; j < 8; ++j) {
            uint32_t jb = kb + j * (8 * APITCH) + koff;
#pragma unroll
            for (int k2 = 0; k2 < 4; ++k2) {
                uint32_t kh[4], kl[4];
                uint32_t a = jb + k2 * 64;
                ldsm_x4(kh, a);
                ldsm_x4(kl, a + ARR_B);
                mma_bf16(sacc[j], qhi[2 * k2], kh);
                mma_bf16(sacc[j], qhi[2 * k2], kl);
                mma_bf16(sacc[j], qlo[2 * k2], kh);
                mma_bf16(sacc[j], qhi[2 * k2 + 1], kh + 2);
                mma_bf16(sacc[j], qhi[2 * k2 + 1], kl + 2);
                mma_bf16(sacc[j], qlo[2 * k2 + 1], kh + 2);
            }
        }

#pragma unroll
        for (int j = 0; j < 8; ++j) {
            int sb0 = s0 + j * 8 + cc;
#pragma unroll
            for (int cx = 0; cx < 2; ++cx) {
                int s = sb0 + cx;
                bool v0 = (tr0 < MMETA) ? (s <= tr0)
                                        : ((s < MMETA) || ((s <= tr0) && (tr0 - s < WWIN)));
                bool v1 = (tr1 < MMETA) ? (s <= tr1)
                                        : ((s < MMETA) || ((s <= tr1) && (tr1 - s < WWIN)));
                if (!v0) sacc[j][cx]     = NEGV;
                if (!v1) sacc[j][cx + 2] = NEGV;
            }
        }

        float mx0 = NEGV, mx1 = NEGV;
#pragma unroll
        for (int j = 0; j < 8; ++j) {
            mx0 = fmaxf(mx0, fmaxf(sacc[j][0], sacc[j][1]));
            mx1 = fmaxf(mx1, fmaxf(sacc[j][2], sacc[j][3]));
        }
        mx0 = fmaxf(mx0, __shfl_xor_sync(0xffffffffu, mx0, 1));
        mx0 = fmaxf(mx0, __shfl_xor_sync(0xffffffffu, mx0, 2));
        mx1 = fmaxf(mx1, __shfl_xor_sync(0xffffffffu, mx1, 1));
        mx1 = fmaxf(mx1, __shfl_xor_sync(0xffffffffu, mx1, 2));

        float mn0 = fmaxf(m0, mx0);
        float mn1 = fmaxf(m1, mx1);
        float al0 = __expf(m0 - mn0);
        float al1 = __expf(m1 - mn1);
        m0 = mn0; m1 = mn1;

        float sum0 = 0.f, sum1 = 0.f;
#pragma unroll
        for (int j = 0; j < 8; ++j) {
            sacc[j][0] = __expf(sacc[j][0] - m0);
            sacc[j][1] = __expf(sacc[j][1] - m0);
            sacc[j][2] = __expf(sacc[j][2] - m1);
            sacc[j][3] = __expf(sacc[j][3] - m1);
            sum0 += sacc[j][0] + sacc[j][1];
            sum1 += sacc[j][2] + sacc[j][3];
        }
        sum0 += __shfl_xor_sync(0xffffffffu, sum0, 1);
        sum0 += __shfl_xor_sync(0xffffffffu, sum0, 2);
        sum1 += __shfl_xor_sync(0xffffffffu, sum1, 1);
        sum1 += __shfl_xor_sync(0xffffffffu, sum1, 2);
        l0 = l0 * al0 + sum0;
        l1 = l1 * al1 + sum1;

#pragma unroll
        for (int j = 0; j < 16; ++j) {
            oacc[j][0] *= al0; oacc[j][1] *= al0;
            oacc[j][2] *= al1; oacc[j][3] *= al1;
        }

#pragma unroll
        for (int kt = 0; kt < 4; ++kt) {
            uint32_t phi[4], plo[4];
#pragma unroll
            for (int hq = 0; hq < 2; ++hq) {
                const float* sj = sacc[2 * kt + hq];
                uint32_t h0 = cvt_bf16x2(sj[1], sj[0]);
                uint32_t h1 = cvt_bf16x2(sj[3], sj[2]);
                float a0 = __uint_as_float(h0 << 16);
                float a1 = __uint_as_float(h0 & 0xffff0000u);
                float b0 = __uint_as_float(h1 << 16);
                float b1 = __uint_as_float(h1 & 0xffff0000u);
                phi[2 * hq]     = h0;
                phi[2 * hq + 1] = h1;
                plo[2 * hq]     = cvt_bf16x2(sj[1] - a1, sj[0] - a0);
                plo[2 * hq + 1] = cvt_bf16x2(sj[3] - b1, sj[2] - b0);
            }
            uint32_t ktb = vb + kt * (16 * APITCH) + voff;
#pragma unroll
            for (int j2 = 0; j2 < 8; ++j2) {
                uint32_t vh[4], vl[4];
                uint32_t a = ktb + j2 * 32;
                ldsm_x4t(vh, a);
                ldsm_x4t(vl, a + ARR_B);
                mma_bf16(oacc[2 * j2], phi, vh);
                mma_bf16(oacc[2 * j2], phi, vl);
                mma_bf16(oacc[2 * j2], plo, vh);
                mma_bf16(oacc[2 * j2 + 1], phi, vh + 2);
                mma_bf16(oacc[2 * j2 + 1], phi, vl + 2);
                mma_bf16(oacc[2 * j2 + 1], plo, vh + 2);
            }
        }
        buf = (buf == 2) ? 0 : buf + 1;
    }

    float inv0 = 1.0f / l0;
    float inv1 = 1.0f / l1;
    float* ob0 = &out[(size_t)tr0 * (NH * HD) + head * HD + cc];
    float* ob1 = &out[(size_t)tr1 * (NH * HD) + head * HD + cc];
#pragma unroll
    for (int j = 0; j < 16; ++j) {
        float2 v0 = { oacc[j][0] * inv0, oacc[j][1] * inv0 };
        float2 v1 = { oacc[j][2] * inv1, oacc[j][3] * inv1 };
        *(float2*)&ob0[j * 8] = v0;
        *(float2*)&ob1[j * 8] = v1;
    }
}

// ---------------------------------------------------------------------------
extern "C" void kernel_launch(void* const* d_in, const int* in_sizes, int n_in,
                              void* d_out, int out_size) {
    const float* hs   = (const float*)d_in[0];
    const float* w    = (const float*)d_in[1];
    const float* bias = (const float*)d_in[2];
    const int*   pos  = (const int*)d_in[3];
    float* out = (float*)d_out;

    init_invfreq_kernel<<<1, 64>>>();

    int na = T_TOK * HS / 4;
    split_a_kernel<<<(na + 255) / 256, 256>>>(hs);
    split_w_kernel<<<dim3(NQKV / 32, HS / 32), dim3(32, 8)>>>(w);

    cudaFuncSetAttribute(qkv_mma_kernel, cudaFuncAttributeMaxDynamicSharedMemorySize, GEMM_SMEM);
    qkv_mma_kernel<<<dim3(24, T_TOK / 128), 256, GEMM_SMEM>>>(bias, pos);

    cudaFuncSetAttribute(attn_mma_kernel, cudaFuncAttributeMaxDynamicSharedMemorySize, ATTN_SMEM);
    attn_mma_kernel<<<dim3(34, 8), 256, ATTN_SMEM>>>(out);
}

// round 8
// speedup vs baseline: 1.0840x; 1.0840x over previous
#include <cuda_runtime.h>
#include <cuda_bf16.h>
#include <cstdint>
#include <math.h>

#define T_TOK 2176
#define HS    2048
#define NQKV  3072
#define NH    16
#define NKV   4
#define HD    128
#define MMETA 128
#define WWIN  512
#define SCALE_F 0.08838834764831845f
#define NEGV  -1.0e30f

// ---------------------------------------------------------------------------
// scratch buffers
// ---------------------------------------------------------------------------
__device__ float g_qkv[T_TOK * NQKV];                    // Q roped+scaled fp32
__device__ float g_partial[T_TOK * NQKV];                // split-K partial sums
__device__ int   g_cnt[24 * 17];                         // split-K arrival counters
__device__ int   g_flag[24 * 17];                        // split-K data-ready flags
__device__ __nv_bfloat16 g_Ahi[T_TOK * HS];
__device__ __nv_bfloat16 g_Alo[T_TOK * HS];
__device__ __nv_bfloat16 g_Bthi[NQKV * HS];              // W transposed [n][k]
__device__ __nv_bfloat16 g_Btlo[NQKV * HS];
__device__ __nv_bfloat16 g_Khi[T_TOK * NKV * HD];
__device__ __nv_bfloat16 g_Klo[T_TOK * NKV * HD];
__device__ __nv_bfloat16 g_Vhi[T_TOK * NKV * HD];
__device__ __nv_bfloat16 g_Vlo[T_TOK * NKV * HD];
__device__ float g_invfreq[64];

__device__ __forceinline__ uint32_t smem_to_u32(const void* p) {
    uint32_t a;
    asm("{ .reg .u64 t; cvta.to.shared.u64 t, %1; cvt.u32.u64 %0, t; }" : "=r"(a) : "l"(p));
    return a;
}
__device__ __forceinline__ uint32_t cvt_bf16x2(float hi, float lo) {
    uint32_t d;
    asm("cvt.rn.bf16x2.f32 %0, %1, %2;" : "=r"(d) : "f"(hi), "f"(lo));
    return d;
}
__device__ __forceinline__ void ldsm_x4(uint32_t* r, uint32_t addr) {
    asm volatile("ldmatrix.sync.aligned.m8n8.x4.shared.b16 {%0,%1,%2,%3}, [%4];"
                 : "=r"(r[0]), "=r"(r[1]), "=r"(r[2]), "=r"(r[3]) : "r"(addr));
}
__device__ __forceinline__ void ldsm_x4t(uint32_t* r, uint32_t addr) {
    asm volatile("ldmatrix.sync.aligned.m8n8.x4.trans.shared.b16 {%0,%1,%2,%3}, [%4];"
                 : "=r"(r[0]), "=r"(r[1]), "=r"(r[2]), "=r"(r[3]) : "r"(addr));
}
__device__ __forceinline__ void mma_bf16(float* c, const uint32_t* a, const uint32_t* b) {
    asm volatile(
        "mma.sync.aligned.m16n8k16.row.col.f32.bf16.bf16.f32 "
        "{%0,%1,%2,%3}, {%4,%5,%6,%7}, {%8,%9}, {%0,%1,%2,%3};"
        : "+f"(c[0]), "+f"(c[1]), "+f"(c[2]), "+f"(c[3])
        : "r"(a[0]), "r"(a[1]), "r"(a[2]), "r"(a[3]), "r"(b[0]), "r"(b[1]));
}
__device__ __forceinline__ void cp_async16(uint32_t dst, const void* src) {
    asm volatile("cp.async.ca.shared.global [%0], [%1], 16;" :: "r"(dst), "l"(src) : "memory");
}
#define CP_COMMIT() asm volatile("cp.async.commit_group;" ::: "memory")
#define CP_WAIT1()  asm volatile("cp.async.wait_group 1;" ::: "memory")
#define CP_WAIT0()  asm volatile("cp.async.wait_group 0;" ::: "memory")

// ---------------------------------------------------------------------------
__global__ void init_invfreq_kernel() {
    int i = threadIdx.x;
    g_invfreq[i] = (float)exp(-(double)(2 * i) * (1.0 / 128.0) * log(10000.0));
}

__global__ void split_a_kernel(const float* __restrict__ A) {
    int i = (blockIdx.x * blockDim.x + threadIdx.x) * 4;
    if (i >= T_TOK * HS) return;
    float4 v = *(const float4*)&A[i];
    __nv_bfloat16 h0 = __float2bfloat16(v.x);
    __nv_bfloat16 h1 = __float2bfloat16(v.y);
    __nv_bfloat16 h2 = __float2bfloat16(v.z);
    __nv_bfloat16 h3 = __float2bfloat16(v.w);
    __nv_bfloat162 hi01, hi23, lo01, lo23;
    hi01.x = h0; hi01.y = h1; hi23.x = h2; hi23.y = h3;
    lo01.x = __float2bfloat16(v.x - __bfloat162float(h0));
    lo01.y = __float2bfloat16(v.y - __bfloat162float(h1));
    lo23.x = __float2bfloat16(v.z - __bfloat162float(h2));
    lo23.y = __float2bfloat16(v.w - __bfloat162float(h3));
    *(__nv_bfloat162*)&g_Ahi[i]     = hi01;
    *(__nv_bfloat162*)&g_Ahi[i + 2] = hi23;
    *(__nv_bfloat162*)&g_Alo[i]     = lo01;
    *(__nv_bfloat162*)&g_Alo[i + 2] = lo23;
}

__global__ void split_w_kernel(const float* __restrict__ W) {
    __shared__ float tile[32][33];
    int n0 = blockIdx.x * 32;
    int k0 = blockIdx.y * 32;
    int tx = threadIdx.x;
    int ty = threadIdx.y;
#pragma unroll
    for (int p = 0; p < 4; ++p) {
        int k = ty + p * 8;
        tile[k][tx] = W[(size_t)(k0 + k) * NQKV + n0 + tx];
    }
    __syncthreads();
#pragma unroll
    for (int p = 0; p < 4; ++p) {
        int n = ty + p * 8;
        float v = tile[tx][n];
        __nv_bfloat16 hi = __float2bfloat16(v);
        __nv_bfloat16 lo = __float2bfloat16(v - __bfloat162float(hi));
        size_t o = (size_t)(n0 + n) * HS + k0 + tx;
        g_Bthi[o] = hi;
        g_Btlo[o] = lo;
    }
}

// ---------------------------------------------------------------------------
// Stage 1: bf16x3 GEMM, CTA 128x128, 8 warps (64x32), BK=32, 2-stage, occ 2.
// SPLIT-K = 2: grid (24 heads, 17 m-tiles, 2 k-halves).
// First arriver stores raw acc to g_partial; second combines + fused epilogue
// (bias + RoPE + Q-scale + K/V split).
// ---------------------------------------------------------------------------
#define BK 32
#define TILE_B (128 * 80)
#define STAGE_B (4 * TILE_B)
#define GEMM_SMEM (2 * STAGE_B)

__global__ __launch_bounds__(256, 2)
void qkv_mma_kernel(const float* __restrict__ bias, const int* __restrict__ pos) {
    extern __shared__ char smem[];
    const uint32_t sb = smem_to_u32(smem);
    const int tid  = threadIdx.x;
    const int wid  = tid >> 5;
    const int lane = tid & 31;
    const int head = blockIdx.x;            // 0..23
    const int bm = blockIdx.y * 128;
    const int bn = head * 128;
    const int kh = blockIdx.z;              // 0 or 1 (k-half)
    const int koff = kh * (HS / 2);
    const int tile_id = head * 17 + blockIdx.y;
    const int wm = (wid >> 2) * 64;
    const int wn = (wid & 3) * 32;

    const __nv_bfloat16* srcs[4] = {
        g_Ahi + (size_t)bm * HS + koff, g_Alo + (size_t)bm * HS + koff,
        g_Bthi + (size_t)bn * HS + koff, g_Btlo + (size_t)bn * HS + koff };

    auto issue_stage = [&](int c, int s) {
#pragma unroll
        for (int q = 0; q < 8; ++q) {
            int idx = q * 256 + tid;
            int t   = idx >> 9;
            int cc  = idx & 511;
            int row = cc >> 2;
            int seg = cc & 3;
            const __nv_bfloat16* src = srcs[t] + (size_t)row * HS + c * BK + seg * 8;
            uint32_t dst = sb + s * STAGE_B + t * TILE_B + row * 80 + seg * 16;
            cp_async16(dst, src);
        }
    };

    float acc[4][4][4];
#pragma unroll
    for (int i = 0; i < 4; ++i)
#pragma unroll
        for (int j = 0; j < 4; ++j)
#pragma unroll
            for (int q = 0; q < 4; ++q) acc[i][j][q] = 0.f;

    issue_stage(0, 0); CP_COMMIT();
    issue_stage(1, 1); CP_COMMIT();

    const int arow  = wm + (lane & 15);
    const int acolh = (lane >> 4) << 3;
    const int brow4 = (lane & 7) + ((lane >> 4) & 1) * 8;
    const int bcol4 = ((lane >> 3) & 1) * 8;

    const int NCH = HS / 2 / BK;   // 32
    for (int c = 0; c < NCH; ++c) {
        CP_WAIT1();
        __syncthreads();

        const uint32_t base = sb + (c & 1) * STAGE_B;
#pragma unroll
        for (int ks = 0; ks < 2; ++ks) {
            uint32_t ahi[4][4], alo[4][4];
#pragma unroll
            for (int i = 0; i < 4; ++i) {
                uint32_t aaddr = base + (arow + i * 16) * 80 + (acolh + ks * 16) * 2;
                ldsm_x4(ahi[i], aaddr);
                ldsm_x4(alo[i], aaddr + TILE_B);
            }
#pragma unroll
            for (int jp = 0; jp < 2; ++jp) {
                uint32_t bh[4], bl[4];
                uint32_t baddr = base + 2 * TILE_B +
                                 (wn + jp * 16 + brow4) * 80 + (bcol4 + ks * 16) * 2;
                ldsm_x4(bh, baddr);
                ldsm_x4(bl, baddr + TILE_B);
#pragma unroll
                for (int i = 0; i < 4; ++i) {
                    mma_bf16(acc[i][2 * jp], ahi[i], bh);
                    mma_bf16(acc[i][2 * jp], ahi[i], bl);
                    mma_bf16(acc[i][2 * jp], alo[i], bh);
                    mma_bf16(acc[i][2 * jp + 1], ahi[i], bh + 2);
                    mma_bf16(acc[i][2 * jp + 1], ahi[i], bl + 2);
                    mma_bf16(acc[i][2 * jp + 1], alo[i], bh + 2);
                }
            }
        }
        __syncthreads();
        if (c + 2 < NCH) issue_stage(c + 2, c & 1);
        CP_COMMIT();
    }

    CP_WAIT0();
    __syncthreads();

    // ---- split-K arbitration ----
    __shared__ int s_old;
    if (tid == 0) s_old = atomicAdd(&g_cnt[tile_id], 1);
    __syncthreads();

    const int r  = lane >> 2;
    const int cc = (lane & 3) * 2;

    if (s_old == 0) {
        // first arriver: store raw partial, set flag
#pragma unroll
        for (int i = 0; i < 4; ++i) {
#pragma unroll
            for (int j = 0; j < 4; ++j) {
                int col = bn + wn + j * 8 + cc;
                int row0 = bm + wm + i * 16 + r;
                float2 v0 = { acc[i][j][0], acc[i][j][1] };
                float2 v1 = { acc[i][j][2], acc[i][j][3] };
                *(float2*)&g_partial[(size_t)row0 * NQKV + col]       = v0;
                *(float2*)&g_partial[(size_t)(row0 + 8) * NQKV + col] = v1;
            }
        }
        __threadfence();
        __syncthreads();
        if (tid == 0) atomicExch(&g_flag[tile_id], 1);
        return;
    }

    // second arriver: wait for partner data, combine into registers
    if (tid == 0) {
        while (atomicAdd(&g_flag[tile_id], 0) == 0) {}
    }
    __syncthreads();
    __threadfence();

#pragma unroll
    for (int i = 0; i < 4; ++i) {
#pragma unroll
        for (int j = 0; j < 4; ++j) {
            int col = bn + wn + j * 8 + cc;
            int row0 = bm + wm + i * 16 + r;
            float2 p0 = *(const float2*)&g_partial[(size_t)row0 * NQKV + col];
            float2 p1 = *(const float2*)&g_partial[(size_t)(row0 + 8) * NQKV + col];
            acc[i][j][0] += p0.x; acc[i][j][1] += p0.y;
            acc[i][j][2] += p1.x; acc[i][j][3] += p1.y;
        }
    }

    // ---- fused epilogue (bias + RoPE + scale + split) ----
    float* Ct = (float*)smem;                 // [128][132] fp32 = 67584 B
#pragma unroll
    for (int i = 0; i < 4; ++i) {
#pragma unroll
        for (int j = 0; j < 4; ++j) {
            int col = wn + j * 8 + cc;
            float b0 = bias[bn + col], b1 = bias[bn + col + 1];
            int row = wm + i * 16 + r;
            Ct[row * 132 + col]           = acc[i][j][0] + b0;
            Ct[row * 132 + col + 1]       = acc[i][j][1] + b1;
            Ct[(row + 8) * 132 + col]     = acc[i][j][2] + b0;
            Ct[(row + 8) * 132 + col + 1] = acc[i][j][3] + b1;
        }
    }
    __syncthreads();

#pragma unroll 4
    for (int p = 0; p < 32; ++p) {
        int idx = p * 256 + tid;
        int row = idx >> 6;
        int i   = idx & 63;
        int t   = bm + row;
        float x1 = Ct[row * 132 + i];
        float x2 = Ct[row * 132 + i + 64];
        if (head < 20) {
            float ang = (float)pos[t] * g_invfreq[i];
            float c = cosf(ang), s = sinf(ang);
            float y1 = x1 * c - x2 * s;
            float y2 = x2 * c + x1 * s;
            if (head < 16) {
                g_qkv[(size_t)t * NQKV + head * HD + i]      = y1 * SCALE_F;
                g_qkv[(size_t)t * NQKV + head * HD + i + 64] = y2 * SCALE_F;
            } else {
                size_t o = (size_t)t * (NKV * HD) + (head - 16) * HD + i;
                __nv_bfloat16 h1 = __float2bfloat16(y1);
                __nv_bfloat16 h2 = __float2bfloat16(y2);
                g_Khi[o]      = h1;
                g_Khi[o + 64] = h2;
                g_Klo[o]      = __float2bfloat16(y1 - __bfloat162float(h1));
                g_Klo[o + 64] = __float2bfloat16(y2 - __bfloat162float(h2));
            }
        } else {
            size_t o = (size_t)t * (NKV * HD) + (head - 20) * HD + i;
            __nv_bfloat16 h1 = __float2bfloat16(x1);
            __nv_bfloat16 h2 = __float2bfloat16(x2);
            g_Vhi[o]      = h1;
            g_Vhi[o + 64] = h2;
            g_Vlo[o]      = __float2bfloat16(x1 - __bfloat162float(h1));
            g_Vlo[o + 64] = __float2bfloat16(x2 - __bfloat162float(h2));
        }
    }

    // reset flags for next graph replay (kernel boundary orders visibility)
    __syncthreads();
    if (tid == 0) {
        g_cnt[tile_id] = 0;
        g_flag[tile_id] = 0;
    }
}

// ---------------------------------------------------------------------------
// Stage 3: attention via mma.sync (R6 2-stage version).
// ---------------------------------------------------------------------------
#define APITCH 272
#define ARR_B  (64 * APITCH)
#define ASTAGE (4 * ARR_B)
#define ATTN_SMEM (2 * ASTAGE)

__global__ __launch_bounds__(256, 1)
void attn_mma_kernel(float* __restrict__ out) {
    extern __shared__ char smc[];
    const uint32_t smu = smem_to_u32(smc);
    const int tid  = threadIdx.x;
    const int wid  = tid >> 5;
    const int lane = tid & 31;

    const int qt   = 33 - blockIdx.x;
    const int hp   = blockIdx.y;
    const int head = hp * 2 + (wid >> 2);
    const int kvh  = hp >> 1;
    const int t0   = qt * 64;
    const int mrow = (wid & 3) * 16;

    const int r  = lane >> 2;
    const int cc = (lane & 3) * 2;

    int kts[12];
    int nkt = 0;
    if (t0 >= MMETA && qt >= 10) {
        kts[nkt++] = 0; kts[nkt++] = 1;
        for (int k = qt - 8; k <= qt; ++k) kts[nkt++] = k;
    } else {
        for (int k = 0; k <= qt; ++k) kts[nkt++] = k;
    }

    uint32_t qhi[8][4], qlo[8][4];
    {
        const float* qb = &g_qkv[(size_t)(t0 + mrow) * NQKV + head * HD];
#pragma unroll
        for (int ks = 0; ks < 8; ++ks) {
#pragma unroll
            for (int rg = 0; rg < 4; ++rg) {
                int row = r + (rg & 1) * 8;
                int col = ks * 16 + cc + (rg >> 1) * 8;
                float2 v = *(const float2*)&qb[(size_t)row * NQKV + col];
                uint32_t h = cvt_bf16x2(v.y, v.x);
                float f0 = __uint_as_float(h << 16);
                float f1 = __uint_as_float(h & 0xffff0000u);
                qhi[ks][rg] = h;
                qlo[ks][rg] = cvt_bf16x2(v.y - f1, v.x - f0);
            }
        }
    }

    const __nv_bfloat16* srcKV[4] = { g_Khi, g_Klo, g_Vhi, g_Vlo };
    auto issue = [&](int ti, int buf) {
        int s0 = kts[ti] * 64;
#pragma unroll
        for (int q = 0; q < 16; ++q) {
            int idx = q * 256 + tid;
            int arr = idx >> 10;
            int rem = idx & 1023;
            int row = rem >> 4;
            int ch  = rem & 15;
            const __nv_bfloat16* src = srcKV[arr] + (size_t)(s0 + row) * (NKV * HD) + kvh * HD + ch * 8;
            uint32_t dst = smu + buf * ASTAGE + arr * ARR_B + row * APITCH + ch * 16;
            cp_async16(dst, src);
        }
    };

    const uint32_t koff = (lane & 7) * APITCH + (lane >> 3) * 16;
    const uint32_t voff = ((lane & 7) + ((lane >> 3) & 1) * 8) * APITCH + ((lane >> 3) >> 1) * 16;

    float oacc[16][4];
#pragma unroll
    for (int j = 0; j < 16; ++j)
#pragma unroll
        for (int q = 0; q < 4; ++q) oacc[j][q] = 0.f;
    float m0 = -3.0e38f, m1 = -3.0e38f, l0 = 0.f, l1 = 0.f;

    const int tr0 = t0 + mrow + r;
    const int tr1 = tr0 + 8;

    issue(0, 0); CP_COMMIT();

    for (int it = 0; it < nkt; ++it) {
        if (it + 1 < nkt) issue(it + 1, (it + 1) & 1);
        CP_COMMIT();
        CP_WAIT1();
        __syncthreads();

        const uint32_t kb = smu + (it & 1) * ASTAGE;
        const uint32_t vb = kb + 2 * ARR_B;
        const int s0 = kts[it] * 64;

        float sacc[8][4];
#pragma unroll
        for (int j = 0; j < 8; ++j)
#pragma unroll
            for (int q = 0; q < 4; ++q) sacc[j][q] = 0.f;

#pragma unroll
        for (int j = 0; j < 8; ++j) {
            uint32_t jb = kb + j * (8 * APITCH) + koff;
#pragma unroll
            for (int k2 = 0; k2 < 4; ++k2) {
                uint32_t kh[4], kl[4];
                uint32_t a = jb + k2 * 64;
                ldsm_x4(kh, a);
                ldsm_x4(kl, a + ARR_B);
                mma_bf16(sacc[j], qhi[2 * k2], kh);
                mma_bf16(sacc[j], qhi[2 * k2], kl);
                mma_bf16(sacc[j], qlo[2 * k2], kh);
                mma_bf16(sacc[j], qhi[2 * k2 + 1], kh + 2);
                mma_bf16(sacc[j], qhi[2 * k2 + 1], kl + 2);
                mma_bf16(sacc[j], qlo[2 * k2 + 1], kh + 2);
            }
        }

#pragma unroll
        for (int j = 0; j < 8; ++j) {
            int sb0 = s0 + j * 8 + cc;
#pragma unroll
            for (int cx = 0; cx < 2; ++cx) {
                int s = sb0 + cx;
                bool v0 = (tr0 < MMETA) ? (s <= tr0)
                                        : ((s < MMETA) || ((s <= tr0) && (tr0 - s < WWIN)));
                bool v1 = (tr1 < MMETA) ? (s <= tr1)
                                        : ((s < MMETA) || ((s <= tr1) && (tr1 - s < WWIN)));
                if (!v0) sacc[j][cx]     = NEGV;
                if (!v1) sacc[j][cx + 2] = NEGV;
            }
        }

        float mx0 = NEGV, mx1 = NEGV;
#pragma unroll
        for (int j = 0; j < 8; ++j) {
            mx0 = fmaxf(mx0, fmaxf(sacc[j][0], sacc[j][1]));
            mx1 = fmaxf(mx1, fmaxf(sacc[j][2], sacc[j][3]));
        }
        mx0 = fmaxf(mx0, __shfl_xor_sync(0xffffffffu, mx0, 1));
        mx0 = fmaxf(mx0, __shfl_xor_sync(0xffffffffu, mx0, 2));
        mx1 = fmaxf(mx1, __shfl_xor_sync(0xffffffffu, mx1, 1));
        mx1 = fmaxf(mx1, __shfl_xor_sync(0xffffffffu, mx1, 2));

        float mn0 = fmaxf(m0, mx0);
        float mn1 = fmaxf(m1, mx1);
        float al0 = __expf(m0 - mn0);
        float al1 = __expf(m1 - mn1);
        m0 = mn0; m1 = mn1;

        float sum0 = 0.f, sum1 = 0.f;
#pragma unroll
        for (int j = 0; j < 8; ++j) {
            sacc[j][0] = __expf(sacc[j][0] - m0);
            sacc[j][1] = __expf(sacc[j][1] - m0);
            sacc[j][2] = __expf(sacc[j][2] - m1);
            sacc[j][3] = __expf(sacc[j][3] - m1);
            sum0 += sacc[j][0] + sacc[j][1];
            sum1 += sacc[j][2] + sacc[j][3];
        }
        sum0 += __shfl_xor_sync(0xffffffffu, sum0, 1);
        sum0 += __shfl_xor_sync(0xffffffffu, sum0, 2);
        sum1 += __shfl_xor_sync(0xffffffffu, sum1, 1);
        sum1 += __shfl_xor_sync(0xffffffffu, sum1, 2);
        l0 = l0 * al0 + sum0;
        l1 = l1 * al1 + sum1;

#pragma unroll
        for (int j = 0; j < 16; ++j) {
            oacc[j][0] *= al0; oacc[j][1] *= al0;
            oacc[j][2] *= al1; oacc[j][3] *= al1;
        }

#pragma unroll
        for (int kt = 0; kt < 4; ++kt) {
            uint32_t phi[4], plo[4];
#pragma unroll
            for (int hq = 0; hq < 2; ++hq) {
                const float* sj = sacc[2 * kt + hq];
                uint32_t h0 = cvt_bf16x2(sj[1], sj[0]);
                uint32_t h1 = cvt_bf16x2(sj[3], sj[2]);
                float a0 = __uint_as_float(h0 << 16);
                float a1 = __uint_as_float(h0 & 0xffff0000u);
                float b0 = __uint_as_float(h1 << 16);
                float b1 = __uint_as_float(h1 & 0xffff0000u);
                phi[2 * hq]     = h0;
                phi[2 * hq + 1] = h1;
                plo[2 * hq]     = cvt_bf16x2(sj[1] - a1, sj[0] - a0);
                plo[2 * hq + 1] = cvt_bf16x2(sj[3] - b1, sj[2] - b0);
            }
            uint32_t ktb = vb + kt * (16 * APITCH) + voff;
#pragma unroll
            for (int j2 = 0; j2 < 8; ++j2) {
                uint32_t vh[4], vl[4];
                uint32_t a = ktb + j2 * 32;
                ldsm_x4t(vh, a);
                ldsm_x4t(vl, a + ARR_B);
                mma_bf16(oacc[2 * j2], phi, vh);
                mma_bf16(oacc[2 * j2], phi, vl);
                mma_bf16(oacc[2 * j2], plo, vh);
                mma_bf16(oacc[2 * j2 + 1], phi, vh + 2);
                mma_bf16(oacc[2 * j2 + 1], phi, vl + 2);
                mma_bf16(oacc[2 * j2 + 1], plo, vh + 2);
            }
        }
        __syncthreads();
    }

    float inv0 = 1.0f / l0;
    float inv1 = 1.0f / l1;
    float* ob0 = &out[(size_t)tr0 * (NH * HD) + head * HD + cc];
    float* ob1 = &out[(size_t)tr1 * (NH * HD) + head * HD + cc];
#pragma unroll
    for (int j = 0; j < 16; ++j) {
        float2 v0 = { oacc[j][0] * inv0, oacc[j][1] * inv0 };
        float2 v1 = { oacc[j][2] * inv1, oacc[j][3] * inv1 };
        *(float2*)&ob0[j * 8] = v0;
        *(float2*)&ob1[j * 8] = v1;
    }
}

// ---------------------------------------------------------------------------
extern "C" void kernel_launch(void* const* d_in, const int* in_sizes, int n_in,
                              void* d_out, int out_size) {
    const float* hs   = (const float*)d_in[0];
    const float* w    = (const float*)d_in[1];
    const float* bias = (const float*)d_in[2];
    const int*   pos  = (const int*)d_in[3];
    float* out = (float*)d_out;

    init_invfreq_kernel<<<1, 64>>>();

    int na = T_TOK * HS / 4;
    split_a_kernel<<<(na + 255) / 256, 256>>>(hs);
    split_w_kernel<<<dim3(NQKV / 32, HS / 32), dim3(32, 8)>>>(w);

    cudaFuncSetAttribute(qkv_mma_kernel, cudaFuncAttributeMaxDynamicSharedMemorySize, GEMM_SMEM);
    qkv_mma_kernel<<<dim3(24, T_TOK / 128, 2), 256, GEMM_SMEM>>>(bias, pos);

    cudaFuncSetAttribute(attn_mma_kernel, cudaFuncAttributeMaxDynamicSharedMemorySize, ATTN_SMEM);
    attn_mma_kernel<<<dim3(34, 8), 256, ATTN_SMEM>>>(out);
}

// round 9
// speedup vs baseline: 1.1039x; 1.0183x over previous
#include <cuda_runtime.h>
#include <cuda_bf16.h>
#include <cstdint>
#include <math.h>

#define T_TOK 2176
#define HS    2048
#define NQKV  3072
#define NH    16
#define NKV   4
#define HD    128
#define MMETA 128
#define WWIN  512
#define SCALE_F 0.08838834764831845f
#define NEGV  -1.0e30f

// ---------------------------------------------------------------------------
// scratch buffers
// ---------------------------------------------------------------------------
__device__ float g_qkv[T_TOK * NQKV];                    // Q roped+scaled fp32
__device__ __nv_bfloat16 g_Ahi[T_TOK * HS];
__device__ __nv_bfloat16 g_Alo[T_TOK * HS];
__device__ __nv_bfloat16 g_Bthi[NQKV * HS];              // W transposed [n][k]
__device__ __nv_bfloat16 g_Btlo[NQKV * HS];
__device__ __nv_bfloat16 g_Khi[T_TOK * NKV * HD];
__device__ __nv_bfloat16 g_Klo[T_TOK * NKV * HD];
__device__ __nv_bfloat16 g_Vhi[T_TOK * NKV * HD];
__device__ __nv_bfloat16 g_Vlo[T_TOK * NKV * HD];
__device__ float g_invfreq[64];

__device__ __forceinline__ uint32_t smem_to_u32(const void* p) {
    uint32_t a;
    asm("{ .reg .u64 t; cvta.to.shared.u64 t, %1; cvt.u32.u64 %0, t; }" : "=r"(a) : "l"(p));
    return a;
}
__device__ __forceinline__ uint32_t cvt_bf16x2(float hi, float lo) {
    uint32_t d;
    asm("cvt.rn.bf16x2.f32 %0, %1, %2;" : "=r"(d) : "f"(hi), "f"(lo));
    return d;
}
__device__ __forceinline__ void ldsm_x4(uint32_t* r, uint32_t addr) {
    asm volatile("ldmatrix.sync.aligned.m8n8.x4.shared.b16 {%0,%1,%2,%3}, [%4];"
                 : "=r"(r[0]), "=r"(r[1]), "=r"(r[2]), "=r"(r[3]) : "r"(addr));
}
__device__ __forceinline__ void ldsm_x4t(uint32_t* r, uint32_t addr) {
    asm volatile("ldmatrix.sync.aligned.m8n8.x4.trans.shared.b16 {%0,%1,%2,%3}, [%4];"
                 : "=r"(r[0]), "=r"(r[1]), "=r"(r[2]), "=r"(r[3]) : "r"(addr));
}
__device__ __forceinline__ void mma_bf16(float* c, const uint32_t* a, const uint32_t* b) {
    asm volatile(
        "mma.sync.aligned.m16n8k16.row.col.f32.bf16.bf16.f32 "
        "{%0,%1,%2,%3}, {%4,%5,%6,%7}, {%8,%9}, {%0,%1,%2,%3};"
        : "+f"(c[0]), "+f"(c[1]), "+f"(c[2]), "+f"(c[3])
        : "r"(a[0]), "r"(a[1]), "r"(a[2]), "r"(a[3]), "r"(b[0]), "r"(b[1]));
}
__device__ __forceinline__ void cp_async16(uint32_t dst, const void* src) {
    asm volatile("cp.async.ca.shared.global [%0], [%1], 16;" :: "r"(dst), "l"(src) : "memory");
}
#define CP_COMMIT() asm volatile("cp.async.commit_group;" ::: "memory")
#define CP_WAIT1()  asm volatile("cp.async.wait_group 1;" ::: "memory")
#define CP_WAIT0()  asm volatile("cp.async.wait_group 0;" ::: "memory")

// ---------------------------------------------------------------------------
__global__ void init_invfreq_kernel() {
    int i = threadIdx.x;
    g_invfreq[i] = (float)exp(-(double)(2 * i) * (1.0 / 128.0) * log(10000.0));
}

__global__ void split_a_kernel(const float* __restrict__ A) {
    int i = (blockIdx.x * blockDim.x + threadIdx.x) * 4;
    if (i >= T_TOK * HS) return;
    float4 v = *(const float4*)&A[i];
    __nv_bfloat16 h0 = __float2bfloat16(v.x);
    __nv_bfloat16 h1 = __float2bfloat16(v.y);
    __nv_bfloat16 h2 = __float2bfloat16(v.z);
    __nv_bfloat16 h3 = __float2bfloat16(v.w);
    __nv_bfloat162 hi01, hi23, lo01, lo23;
    hi01.x = h0; hi01.y = h1; hi23.x = h2; hi23.y = h3;
    lo01.x = __float2bfloat16(v.x - __bfloat162float(h0));
    lo01.y = __float2bfloat16(v.y - __bfloat162float(h1));
    lo23.x = __float2bfloat16(v.z - __bfloat162float(h2));
    lo23.y = __float2bfloat16(v.w - __bfloat162float(h3));
    *(__nv_bfloat162*)&g_Ahi[i]     = hi01;
    *(__nv_bfloat162*)&g_Ahi[i + 2] = hi23;
    *(__nv_bfloat162*)&g_Alo[i]     = lo01;
    *(__nv_bfloat162*)&g_Alo[i + 2] = lo23;
}

__global__ void split_w_kernel(const float* __restrict__ W) {
    __shared__ float tile[32][33];
    int n0 = blockIdx.x * 32;
    int k0 = blockIdx.y * 32;
    int tx = threadIdx.x;
    int ty = threadIdx.y;
#pragma unroll
    for (int p = 0; p < 4; ++p) {
        int k = ty + p * 8;
        tile[k][tx] = W[(size_t)(k0 + k) * NQKV + n0 + tx];
    }
    __syncthreads();
#pragma unroll
    for (int p = 0; p < 4; ++p) {
        int n = ty + p * 8;
        float v = tile[tx][n];
        __nv_bfloat16 hi = __float2bfloat16(v);
        __nv_bfloat16 lo = __float2bfloat16(v - __bfloat162float(hi));
        size_t o = (size_t)(n0 + n) * HS + k0 + tx;
        g_Bthi[o] = hi;
        g_Btlo[o] = lo;
    }
}

// ---------------------------------------------------------------------------
// Stage 1: bf16x3 GEMM, CTA 128x128, 8 warps (64x32), BK=32.
// 3-stage cp.async pipeline at OCCUPANCY 2 via swizzled pitch-64 tiles
// (no pad; chunk ^= (row>>1)&3). ONE barrier per chunk.
// Fused epilogue: bias + RoPE + Q-scale + K/V split.
// ---------------------------------------------------------------------------
#define BK 32
#define TILE_B (128 * 64)             // 8192
#define STAGE_B (4 * TILE_B)          // 32768
#define GEMM_SMEM (3 * STAGE_B)       // 98304

#define SWB(row, chunk) ((row) * 64 + (((chunk) ^ (((row) >> 1) & 3)) << 4))

__global__ __launch_bounds__(256, 2)
void qkv_mma_kernel(const float* __restrict__ bias, const int* __restrict__ pos) {
    extern __shared__ char smem[];
    const uint32_t sb = smem_to_u32(smem);
    const int tid  = threadIdx.x;
    const int wid  = tid >> 5;
    const int lane = tid & 31;
    const int head = blockIdx.x;            // 0..23
    const int bm = blockIdx.y * 128;
    const int bn = head * 128;
    const int wm = (wid >> 2) * 64;
    const int wn = (wid & 3) * 32;

    const __nv_bfloat16* srcs[4] = {
        g_Ahi + (size_t)bm * HS, g_Alo + (size_t)bm * HS,
        g_Bthi + (size_t)bn * HS, g_Btlo + (size_t)bn * HS };

    // loader: 2048 16B chunks/stage, 8 per thread
    auto issue_stage = [&](int c, int s) {
#pragma unroll
        for (int q = 0; q < 8; ++q) {
            int idx = q * 256 + tid;
            int t   = idx >> 9;
            int rem = idx & 511;
            int row = rem >> 2;
            int seg = rem & 3;
            const __nv_bfloat16* src = srcs[t] + (size_t)row * HS + c * BK + seg * 8;
            uint32_t dst = sb + s * STAGE_B + t * TILE_B + SWB(row, seg);
            cp_async16(dst, src);
        }
    };

    float acc[4][4][4];
#pragma unroll
    for (int i = 0; i < 4; ++i)
#pragma unroll
        for (int j = 0; j < 4; ++j)
#pragma unroll
            for (int q = 0; q < 4; ++q) acc[i][j][q] = 0.f;

    issue_stage(0, 0); CP_COMMIT();
    issue_stage(1, 1); CP_COMMIT();

    const int arow  = wm + (lane & 15);
    const int ac0   = lane >> 4;            // A chunk base (0/1)
    const int brow4 = (lane & 7) + ((lane >> 4) & 1) * 8;
    const int bc0   = (lane >> 3) & 1;      // B chunk base (0/1)

    const int NCH = HS / BK;   // 64
    int buf = 0;
    for (int c = 0; c < NCH; ++c) {
        CP_WAIT1();
        __syncthreads();                    // stage c ready; buf (c-1)%3 free

        if (c + 2 < NCH) {
            int nb = buf - 1;               // (c+2)%3 == (c-1)%3
            if (nb < 0) nb = 2;
            issue_stage(c + 2, nb);
        }
        CP_COMMIT();

        const uint32_t base = sb + buf * STAGE_B;
#pragma unroll
        for (int ks = 0; ks < 2; ++ks) {
            uint32_t ahi[4][4], alo[4][4];
#pragma unroll
            for (int i = 0; i < 4; ++i) {
                int row = arow + i * 16;
                uint32_t ad = base + SWB(row, ac0 + ks * 2);
                ldsm_x4(ahi[i], ad);
                ldsm_x4(alo[i], ad + TILE_B);
            }
#pragma unroll
            for (int jp = 0; jp < 2; ++jp) {
                uint32_t bh[4], bl[4];
                int row = wn + jp * 16 + brow4;
                uint32_t bd = base + 2 * TILE_B + SWB(row, bc0 + ks * 2);
                ldsm_x4(bh, bd);
                ldsm_x4(bl, bd + TILE_B);
#pragma unroll
                for (int i = 0; i < 4; ++i) {
                    mma_bf16(acc[i][2 * jp], ahi[i], bh);
                    mma_bf16(acc[i][2 * jp], ahi[i], bl);
                    mma_bf16(acc[i][2 * jp], alo[i], bh);
                    mma_bf16(acc[i][2 * jp + 1], ahi[i], bh + 2);
                    mma_bf16(acc[i][2 * jp + 1], ahi[i], bl + 2);
                    mma_bf16(acc[i][2 * jp + 1], alo[i], bh + 2);
                }
            }
        }
        buf = (buf == 2) ? 0 : buf + 1;
    }

    // ---- fused epilogue ----
    CP_WAIT0();
    __syncthreads();
    float* Ct = (float*)smem;                 // [128][132] fp32 = 67584 B
    const int r  = lane >> 2;
    const int cc = (lane & 3) * 2;
#pragma unroll
    for (int i = 0; i < 4; ++i) {
#pragma unroll
        for (int j = 0; j < 4; ++j) {
            int col = wn + j * 8 + cc;
            float b0 = bias[bn + col], b1 = bias[bn + col + 1];
            int row = wm + i * 16 + r;
            Ct[row * 132 + col]           = acc[i][j][0] + b0;
            Ct[row * 132 + col + 1]       = acc[i][j][1] + b1;
            Ct[(row + 8) * 132 + col]     = acc[i][j][2] + b0;
            Ct[(row + 8) * 132 + col + 1] = acc[i][j][3] + b1;
        }
    }
    __syncthreads();

#pragma unroll 4
    for (int p = 0; p < 32; ++p) {
        int idx = p * 256 + tid;
        int row = idx >> 6;
        int i   = idx & 63;
        int t   = bm + row;
        float x1 = Ct[row * 132 + i];
        float x2 = Ct[row * 132 + i + 64];
        if (head < 20) {
            float ang = (float)pos[t] * g_invfreq[i];
            float c = cosf(ang), s = sinf(ang);
            float y1 = x1 * c - x2 * s;
            float y2 = x2 * c + x1 * s;
            if (head < 16) {
                g_qkv[(size_t)t * NQKV + head * HD + i]      = y1 * SCALE_F;
                g_qkv[(size_t)t * NQKV + head * HD + i + 64] = y2 * SCALE_F;
            } else {
                size_t o = (size_t)t * (NKV * HD) + (head - 16) * HD + i;
                __nv_bfloat16 h1 = __float2bfloat16(y1);
                __nv_bfloat16 h2 = __float2bfloat16(y2);
                g_Khi[o]      = h1;
                g_Khi[o + 64] = h2;
                g_Klo[o]      = __float2bfloat16(y1 - __bfloat162float(h1));
                g_Klo[o + 64] = __float2bfloat16(y2 - __bfloat162float(h2));
            }
        } else {
            size_t o = (size_t)t * (NKV * HD) + (head - 20) * HD + i;
            __nv_bfloat16 h1 = __float2bfloat16(x1);
            __nv_bfloat16 h2 = __float2bfloat16(x2);
            g_Vhi[o]      = h1;
            g_Vhi[o + 64] = h2;
            g_Vlo[o]      = __float2bfloat16(x1 - __bfloat162float(h1));
            g_Vlo[o + 64] = __float2bfloat16(x2 - __bfloat162float(h2));
        }
    }
}

// ---------------------------------------------------------------------------
// Stage 3: attention via mma.sync (R6 2-stage version).
// ---------------------------------------------------------------------------
#define APITCH 272
#define ARR_B  (64 * APITCH)
#define ASTAGE (4 * ARR_B)
#define ATTN_SMEM (2 * ASTAGE)

__global__ __launch_bounds__(256, 1)
void attn_mma_kernel(float* __restrict__ out) {
    extern __shared__ char smc[];
    const uint32_t smu = smem_to_u32(smc);
    const int tid  = threadIdx.x;
    const int wid  = tid >> 5;
    const int lane = tid & 31;

    const int qt   = 33 - blockIdx.x;
    const int hp   = blockIdx.y;
    const int head = hp * 2 + (wid >> 2);
    const int kvh  = hp >> 1;
    const int t0   = qt * 64;
    const int mrow = (wid & 3) * 16;

    const int r  = lane >> 2;
    const int cc = (lane & 3) * 2;

    int kts[12];
    int nkt = 0;
    if (t0 >= MMETA && qt >= 10) {
        kts[nkt++] = 0; kts[nkt++] = 1;
        for (int k = qt - 8; k <= qt; ++k) kts[nkt++] = k;
    } else {
        for (int k = 0; k <= qt; ++k) kts[nkt++] = k;
    }

    uint32_t qhi[8][4], qlo[8][4];
    {
        const float* qb = &g_qkv[(size_t)(t0 + mrow) * NQKV + head * HD];
#pragma unroll
        for (int ks = 0; ks < 8; ++ks) {
#pragma unroll
            for (int rg = 0; rg < 4; ++rg) {
                int row = r + (rg & 1) * 8;
                int col = ks * 16 + cc + (rg >> 1) * 8;
                float2 v = *(const float2*)&qb[(size_t)row * NQKV + col];
                uint32_t h = cvt_bf16x2(v.y, v.x);
                float f0 = __uint_as_float(h << 16);
                float f1 = __uint_as_float(h & 0xffff0000u);
                qhi[ks][rg] = h;
                qlo[ks][rg] = cvt_bf16x2(v.y - f1, v.x - f0);
            }
        }
    }

    const __nv_bfloat16* srcKV[4] = { g_Khi, g_Klo, g_Vhi, g_Vlo };
    auto issue = [&](int ti, int buf) {
        int s0 = kts[ti] * 64;
#pragma unroll
        for (int q = 0; q < 16; ++q) {
            int idx = q * 256 + tid;
            int arr = idx >> 10;
            int rem = idx & 1023;
            int row = rem >> 4;
            int ch  = rem & 15;
            const __nv_bfloat16* src = srcKV[arr] + (size_t)(s0 + row) * (NKV * HD) + kvh * HD + ch * 8;
            uint32_t dst = smu + buf * ASTAGE + arr * ARR_B + row * APITCH + ch * 16;
            cp_async16(dst, src);
        }
    };

    const uint32_t koff = (lane & 7) * APITCH + (lane >> 3) * 16;
    const uint32_t voff = ((lane & 7) + ((lane >> 3) & 1) * 8) * APITCH + ((lane >> 3) >> 1) * 16;

    float oacc[16][4];
#pragma unroll
    for (int j = 0; j < 16; ++j)
#pragma unroll
        for (int q = 0; q < 4; ++q) oacc[j][q] = 0.f;
    float m0 = -3.0e38f, m1 = -3.0e38f, l0 = 0.f, l1 = 0.f;

    const int tr0 = t0 + mrow + r;
    const int tr1 = tr0 + 8;

    issue(0, 0); CP_COMMIT();

    for (int it = 0; it < nkt; ++it) {
        if (it + 1 < nkt) issue(it + 1, (it + 1) & 1);
        CP_COMMIT();
        CP_WAIT1();
        __syncthreads();

        const uint32_t kb = smu + (it & 1) * ASTAGE;
        const uint32_t vb = kb + 2 * ARR_B;
        const int s0 = kts[it] * 64;

        float sacc[8][4];
#pragma unroll
        for (int j = 0; j < 8; ++j)
#pragma unroll
            for (int q = 0; q < 4; ++q) sacc[j][q] = 0.f;

#pragma unroll
        for (int j = 0; j < 8; ++j) {
            uint32_t jb = kb + j * (8 * APITCH) + koff;
#pragma unroll
            for (int k2 = 0; k2 < 4; ++k2) {
                uint32_t kh[4], kl[4];
                uint32_t a = jb + k2 * 64;
                ldsm_x4(kh, a);
                ldsm_x4(kl, a + ARR_B);
                mma_bf16(sacc[j], qhi[2 * k2], kh);
                mma_bf16(sacc[j], qhi[2 * k2], kl);
                mma_bf16(sacc[j], qlo[2 * k2], kh);
                mma_bf16(sacc[j], qhi[2 * k2 + 1], kh + 2);
                mma_bf16(sacc[j], qhi[2 * k2 + 1], kl + 2);
                mma_bf16(sacc[j], qlo[2 * k2 + 1], kh + 2);
            }
        }

#pragma unroll
        for (int j = 0; j < 8; ++j) {
            int sb0 = s0 + j * 8 + cc;
#pragma unroll
            for (int cx = 0; cx < 2; ++cx) {
                int s = sb0 + cx;
                bool v0 = (tr0 < MMETA) ? (s <= tr0)
                                        : ((s < MMETA) || ((s <= tr0) && (tr0 - s < WWIN)));
                bool v1 = (tr1 < MMETA) ? (s <= tr1)
                                        : ((s < MMETA) || ((s <= tr1) && (tr1 - s < WWIN)));
                if (!v0) sacc[j][cx]     = NEGV;
                if (!v1) sacc[j][cx + 2] = NEGV;
            }
        }

        float mx0 = NEGV, mx1 = NEGV;
#pragma unroll
        for (int j = 0; j < 8; ++j) {
            mx0 = fmaxf(mx0, fmaxf(sacc[j][0], sacc[j][1]));
            mx1 = fmaxf(mx1, fmaxf(sacc[j][2], sacc[j][3]));
        }
        mx0 = fmaxf(mx0, __shfl_xor_sync(0xffffffffu, mx0, 1));
        mx0 = fmaxf(mx0, __shfl_xor_sync(0xffffffffu, mx0, 2));
        mx1 = fmaxf(mx1, __shfl_xor_sync(0xffffffffu, mx1, 1));
        mx1 = fmaxf(mx1, __shfl_xor_sync(0xffffffffu, mx1, 2));

        float mn0 = fmaxf(m0, mx0);
        float mn1 = fmaxf(m1, mx1);
        float al0 = __expf(m0 - mn0);
        float al1 = __expf(m1 - mn1);
        m0 = mn0; m1 = mn1;

        float sum0 = 0.f, sum1 = 0.f;
#pragma unroll
        for (int j = 0; j < 8; ++j) {
            sacc[j][0] = __expf(sacc[j][0] - m0);
            sacc[j][1] = __expf(sacc[j][1] - m0);
            sacc[j][2] = __expf(sacc[j][2] - m1);
            sacc[j][3] = __expf(sacc[j][3] - m1);
            sum0 += sacc[j][0] + sacc[j][1];
            sum1 += sacc[j][2] + sacc[j][3];
        }
        sum0 += __shfl_xor_sync(0xffffffffu, sum0, 1);
        sum0 += __shfl_xor_sync(0xffffffffu, sum0, 2);
        sum1 += __shfl_xor_sync(0xffffffffu, sum1, 1);
        sum1 += __shfl_xor_sync(0xffffffffu, sum1, 2);
        l0 = l0 * al0 + sum0;
        l1 = l1 * al1 + sum1;

#pragma unroll
        for (int j = 0; j < 16; ++j) {
            oacc[j][0] *= al0; oacc[j][1] *= al0;
            oacc[j][2] *= al1; oacc[j][3] *= al1;
        }

#pragma unroll
        for (int kt = 0; kt < 4; ++kt) {
            uint32_t phi[4], plo[4];
#pragma unroll
            for (int hq = 0; hq < 2; ++hq) {
                const float* sj = sacc[2 * kt + hq];
                uint32_t h0 = cvt_bf16x2(sj[1], sj[0]);
                uint32_t h1 = cvt_bf16x2(sj[3], sj[2]);
                float a0 = __uint_as_float(h0 << 16);
                float a1 = __uint_as_float(h0 & 0xffff0000u);
                float b0 = __uint_as_float(h1 << 16);
                float b1 = __uint_as_float(h1 & 0xffff0000u);
                phi[2 * hq]     = h0;
                phi[2 * hq + 1] = h1;
                plo[2 * hq]     = cvt_bf16x2(sj[1] - a1, sj[0] - a0);
                plo[2 * hq + 1] = cvt_bf16x2(sj[3] - b1, sj[2] - b0);
            }
            uint32_t ktb = vb + kt * (16 * APITCH) + voff;
#pragma unroll
            for (int j2 = 0; j2 < 8; ++j2) {
                uint32_t vh[4], vl[4];
                uint32_t a = ktb + j2 * 32;
                ldsm_x4t(vh, a);
                ldsm_x4t(vl, a + ARR_B);
                mma_bf16(oacc[2 * j2], phi, vh);
                mma_bf16(oacc[2 * j2], phi, vl);
                mma_bf16(oacc[2 * j2], plo, vh);
                mma_bf16(oacc[2 * j2 + 1], phi, vh + 2);
                mma_bf16(oacc[2 * j2 + 1], phi, vl + 2);
                mma_bf16(oacc[2 * j2 + 1], plo, vh + 2);
            }
        }
        __syncthreads();
    }

    float inv0 = 1.0f / l0;
    float inv1 = 1.0f / l1;
    float* ob0 = &out[(size_t)tr0 * (NH * HD) + head * HD + cc];
    float* ob1 = &out[(size_t)tr1 * (NH * HD) + head * HD + cc];
#pragma unroll
    for (int j = 0; j < 16; ++j) {
        float2 v0 = { oacc[j][0] * inv0, oacc[j][1] * inv0 };
        float2 v1 = { oacc[j][2] * inv1, oacc[j][3] * inv1 };
        *(float2*)&ob0[j * 8] = v0;
        *(float2*)&ob1[j * 8] = v1;
    }
}

// ---------------------------------------------------------------------------
extern "C" void kernel_launch(void* const* d_in, const int* in_sizes, int n_in,
                              void* d_out, int out_size) {
    const float* hs   = (const float*)d_in[0];
    const float* w    = (const float*)d_in[1];
    const float* bias = (const float*)d_in[2];
    const int*   pos  = (const int*)d_in[3];
    float* out = (float*)d_out;

    init_invfreq_kernel<<<1, 64>>>();

    int na = T_TOK * HS / 4;
    split_a_kernel<<<(na + 255) / 256, 256>>>(hs);
    split_w_kernel<<<dim3(NQKV / 32, HS / 32), dim3(32, 8)>>>(w);

    cudaFuncSetAttribute(qkv_mma_kernel, cudaFuncAttributeMaxDynamicSharedMemorySize, GEMM_SMEM);
    qkv_mma_kernel<<<dim3(24, T_TOK / 128), 256, GEMM_SMEM>>>(bias, pos);

    cudaFuncSetAttribute(attn_mma_kernel, cudaFuncAttributeMaxDynamicSharedMemorySize, ATTN_SMEM);
    attn_mma_kernel<<<dim3(34, 8), 256, ATTN_SMEM>>>(out);
}

// round 10
// speedup vs baseline: 1.4840x; 1.3444x over previous
#include <cuda_runtime.h>
#include <cuda_bf16.h>
#include <cstdint>
#include <math.h>

#define T_TOK 2176
#define HS    2048
#define NQKV  3072
#define NH    16
#define NKV   4
#define HD    128
#define MMETA 128
#define WWIN  512
#define SCALE_F 0.08838834764831845f
#define NEGV  -1.0e30f

// ---------------------------------------------------------------------------
// scratch buffers
// ---------------------------------------------------------------------------
__device__ float g_qkv[T_TOK * NQKV];                    // Q roped+scaled fp32
__device__ int8_t g_A8h[T_TOK * HS];
__device__ int8_t g_A8l[T_TOK * HS];
__device__ int8_t g_W8h[NQKV * HS];                      // W transposed [n][k]
__device__ int8_t g_W8l[NQKV * HS];
__device__ float  g_sA[T_TOK];
__device__ unsigned g_sBbits[NQKV];                      // colmax |W| as float bits
__device__ __nv_bfloat16 g_Khi[T_TOK * NKV * HD];
__device__ __nv_bfloat16 g_Klo[T_TOK * NKV * HD];
__device__ __nv_bfloat16 g_Vhi[T_TOK * NKV * HD];
__device__ __nv_bfloat16 g_Vlo[T_TOK * NKV * HD];
__device__ float g_invfreq[64];

__device__ __forceinline__ uint32_t smem_to_u32(const void* p) {
    uint32_t a;
    asm("{ .reg .u64 t; cvta.to.shared.u64 t, %1; cvt.u32.u64 %0, t; }" : "=r"(a) : "l"(p));
    return a;
}
__device__ __forceinline__ uint32_t cvt_bf16x2(float hi, float lo) {
    uint32_t d;
    asm("cvt.rn.bf16x2.f32 %0, %1, %2;" : "=r"(d) : "f"(hi), "f"(lo));
    return d;
}
__device__ __forceinline__ void ldsm_x4(uint32_t* r, uint32_t addr) {
    asm volatile("ldmatrix.sync.aligned.m8n8.x4.shared.b16 {%0,%1,%2,%3}, [%4];"
                 : "=r"(r[0]), "=r"(r[1]), "=r"(r[2]), "=r"(r[3]) : "r"(addr));
}
__device__ __forceinline__ void ldsm_x4t(uint32_t* r, uint32_t addr) {
    asm volatile("ldmatrix.sync.aligned.m8n8.x4.trans.shared.b16 {%0,%1,%2,%3}, [%4];"
                 : "=r"(r[0]), "=r"(r[1]), "=r"(r[2]), "=r"(r[3]) : "r"(addr));
}
__device__ __forceinline__ void mma_bf16(float* c, const uint32_t* a, const uint32_t* b) {
    asm volatile(
        "mma.sync.aligned.m16n8k16.row.col.f32.bf16.bf16.f32 "
        "{%0,%1,%2,%3}, {%4,%5,%6,%7}, {%8,%9}, {%0,%1,%2,%3};"
        : "+f"(c[0]), "+f"(c[1]), "+f"(c[2]), "+f"(c[3])
        : "r"(a[0]), "r"(a[1]), "r"(a[2]), "r"(a[3]), "r"(b[0]), "r"(b[1]));
}
__device__ __forceinline__ void mma_s8(int* c, const uint32_t* a, const uint32_t* b) {
    asm volatile(
        "mma.sync.aligned.m16n8k32.row.col.s32.s8.s8.s32 "
        "{%0,%1,%2,%3}, {%4,%5,%6,%7}, {%8,%9}, {%0,%1,%2,%3};"
        : "+r"(c[0]), "+r"(c[1]), "+r"(c[2]), "+r"(c[3])
        : "r"(a[0]), "r"(a[1]), "r"(a[2]), "r"(a[3]), "r"(b[0]), "r"(b[1]));
}
__device__ __forceinline__ void cp_async16(uint32_t dst, const void* src) {
    asm volatile("cp.async.ca.shared.global [%0], [%1], 16;" :: "r"(dst), "l"(src) : "memory");
}
#define CP_COMMIT() asm volatile("cp.async.commit_group;" ::: "memory")
#define CP_WAIT1()  asm volatile("cp.async.wait_group 1;" ::: "memory")
#define CP_WAIT0()  asm volatile("cp.async.wait_group 0;" ::: "memory")

// ---------------------------------------------------------------------------
__global__ void init_invfreq_kernel() {
    int i = threadIdx.x;
    g_invfreq[i] = (float)exp(-(double)(2 * i) * (1.0 / 128.0) * log(10000.0));
}

// ---------------------------------------------------------------------------
// quantize A: one block per token row; sA = max|a|/127, digits h + l/256
// ---------------------------------------------------------------------------
__global__ void quant_a_kernel(const float* __restrict__ A) {
    const int t = blockIdx.x;
    const int tid = threadIdx.x;
    __shared__ float red[8];
    const float* row = A + (size_t)t * HS;
    float4 v0 = *(const float4*)&row[tid * 8];
    float4 v1 = *(const float4*)&row[tid * 8 + 4];
    float mx = fmaxf(fmaxf(fabsf(v0.x), fabsf(v0.y)), fmaxf(fabsf(v0.z), fabsf(v0.w)));
    mx = fmaxf(mx, fmaxf(fmaxf(fabsf(v1.x), fabsf(v1.y)), fmaxf(fabsf(v1.z), fabsf(v1.w))));
#pragma unroll
    for (int o = 16; o > 0; o >>= 1) mx = fmaxf(mx, __shfl_xor_sync(0xffffffffu, mx, o));
    if ((tid & 31) == 0) red[tid >> 5] = mx;
    __syncthreads();
    float m = fmaxf(fmaxf(fmaxf(red[0], red[1]), fmaxf(red[2], red[3])),
                    fmaxf(fmaxf(red[4], red[5]), fmaxf(red[6], red[7])));
    m = fmaxf(m, 1e-20f);
    if (tid == 0) g_sA[t] = m * (1.0f / 127.0f);
    float inv = 127.0f / m;

    float a[8] = { v0.x, v0.y, v0.z, v0.w, v1.x, v1.y, v1.z, v1.w };
    char hh[8], ll[8];
#pragma unroll
    for (int u = 0; u < 8; ++u) {
        float x = a[u] * inv;
        float h = rintf(x);
        int l = (int)rintf((x - h) * 256.0f);
        if (l > 127) l = 127;
        hh[u] = (char)(int)h;
        ll[u] = (char)l;
    }
    size_t o = (size_t)t * HS + tid * 8;
    *(uint2*)&g_A8h[o] = *(uint2*)hh;
    *(uint2*)&g_A8l[o] = *(uint2*)ll;
}

// ---------------------------------------------------------------------------
// W column max (idempotent atomicMax on abs-float bits) then quantize+transpose
// ---------------------------------------------------------------------------
__global__ void w_colmax_kernel(const float* __restrict__ W) {
    int col = blockIdx.x * 256 + threadIdx.x;
    int r0  = blockIdx.y * 128;
    float mx = 0.f;
    for (int r = 0; r < 128; ++r)
        mx = fmaxf(mx, fabsf(W[(size_t)(r0 + r) * NQKV + col]));
    atomicMax(&g_sBbits[col], __float_as_uint(mx));
}

__global__ void quant_w_kernel(const float* __restrict__ W) {
    __shared__ float tile[32][33];
    int n0 = blockIdx.x * 32;
    int k0 = blockIdx.y * 32;
    int tx = threadIdx.x;
    int ty = threadIdx.y;
#pragma unroll
    for (int p = 0; p < 4; ++p) {
        int k = ty + p * 8;
        tile[k][tx] = W[(size_t)(k0 + k) * NQKV + n0 + tx];
    }
    __syncthreads();
#pragma unroll
    for (int p = 0; p < 4; ++p) {
        int n = ty + p * 8;
        float m = fmaxf(__uint_as_float(g_sBbits[n0 + n]), 1e-20f);
        float inv = 127.0f / m;
        float x = tile[tx][n] * inv;
        float h = rintf(x);
        int l = (int)rintf((x - h) * 256.0f);
        if (l > 127) l = 127;
        size_t o = (size_t)(n0 + n) * HS + k0 + tx;
        g_W8h[o] = (int8_t)(int)h;
        g_W8l[o] = (int8_t)l;
    }
}

// ---------------------------------------------------------------------------
// Stage 1: int8 2-digit GEMM.  CTA 64x128 (M x N), 8 warps (warp 32x32),
// chunk K=64 int8, 3-stage cp.async, one barrier per chunk, occ 2.
// D = sA*sB*(D1 + D2/256) + bias; fused RoPE/scale/KV-split epilogue.
// ---------------------------------------------------------------------------
#define A_T8 4096                      // 64 rows * 64B
#define B_T8 8192                      // 128 rows * 64B
#define STAGE8 24576                   // Ah, Al, Bh, Bl
#define GEMM_SMEM (3 * STAGE8)         // 73728

#define SWB(row, chunk) ((row) * 64 + ((((chunk) ^ (((row) >> 1) & 3))) << 4))

__global__ __launch_bounds__(256, 2)
void qkv_mma_kernel(const float* __restrict__ bias, const int* __restrict__ pos) {
    extern __shared__ char smem[];
    const uint32_t sb = smem_to_u32(smem);
    const int tid  = threadIdx.x;
    const int wid  = tid >> 5;
    const int lane = tid & 31;
    const int head = blockIdx.x;            // 0..23
    const int bm = blockIdx.y * 64;
    const int bn = head * 128;
    const int wm = (wid >> 2) * 32;         // 0 or 32
    const int wn = (wid & 3) * 32;          // 0,32,64,96

    const int8_t* srcA[2] = { g_A8h + (size_t)bm * HS, g_A8l + (size_t)bm * HS };
    const int8_t* srcB[2] = { g_W8h + (size_t)bn * HS, g_W8l + (size_t)bn * HS };

    // loader: 1536 16B chunks/stage, 6 per thread
    auto issue_stage = [&](int c, int s) {
#pragma unroll
        for (int q = 0; q < 6; ++q) {
            int idx = q * 256 + tid;
            const int8_t* src;
            uint32_t dst;
            if (idx < 512) {
                int arr = idx >> 8;
                int rem = idx & 255;
                int row = rem >> 2, seg = rem & 3;
                src = srcA[arr] + (size_t)row * HS + c * 64 + seg * 16;
                dst = sb + s * STAGE8 + arr * A_T8 + SWB(row, seg);
            } else {
                int arr = (idx - 512) >> 9;
                int rem = idx & 511;
                int row = rem >> 2, seg = rem & 3;
                src = srcB[arr] + (size_t)row * HS + c * 64 + seg * 16;
                dst = sb + s * STAGE8 + 2 * A_T8 + arr * B_T8 + SWB(row, seg);
            }
            cp_async16(dst, src);
        }
    };

    int D1[2][4][4], D2[2][4][4];
#pragma unroll
    for (int i = 0; i < 2; ++i)
#pragma unroll
        for (int j = 0; j < 4; ++j)
#pragma unroll
            for (int q = 0; q < 4; ++q) { D1[i][j][q] = 0; D2[i][j][q] = 0; }

    issue_stage(0, 0); CP_COMMIT();
    issue_stage(1, 1); CP_COMMIT();

    const int arow  = wm + (lane & 15);
    const int ac0   = lane >> 4;            // A chunk base (0/1)
    const int brow4 = (lane & 7) + ((lane >> 4) & 1) * 8;
    const int bc0   = (lane >> 3) & 1;      // B chunk base (0/1)

    const int NCH = HS / 64;   // 32
    int buf = 0;
    for (int c = 0; c < NCH; ++c) {
        CP_WAIT1();
        __syncthreads();

        if (c + 2 < NCH) {
            int nb = buf - 1;
            if (nb < 0) nb = 2;
            issue_stage(c + 2, nb);
        }
        CP_COMMIT();

        const uint32_t base = sb + buf * STAGE8;
#pragma unroll
        for (int ks = 0; ks < 2; ++ks) {
            uint32_t ah[2][4], al[2][4];
#pragma unroll
            for (int i = 0; i < 2; ++i) {
                int row = arow + i * 16;
                uint32_t ad = base + SWB(row, ac0 + ks * 2);
                ldsm_x4(ah[i], ad);
                ldsm_x4(al[i], ad + A_T8);
            }
#pragma unroll
            for (int jp = 0; jp < 2; ++jp) {
                uint32_t bh[4], bl[4];
                int row = wn + jp * 16 + brow4;
                uint32_t bd = base + 2 * A_T8 + SWB(row, bc0 + ks * 2);
                ldsm_x4(bh, bd);
                ldsm_x4(bl, bd + B_T8);
#pragma unroll
                for (int i = 0; i < 2; ++i) {
                    mma_s8(D1[i][2 * jp], ah[i], bh);
                    mma_s8(D2[i][2 * jp], ah[i], bl);
                    mma_s8(D2[i][2 * jp], al[i], bh);
                    mma_s8(D1[i][2 * jp + 1], ah[i], bh + 2);
                    mma_s8(D2[i][2 * jp + 1], ah[i], bl + 2);
                    mma_s8(D2[i][2 * jp + 1], al[i], bh + 2);
                }
            }
        }
        buf = (buf == 2) ? 0 : buf + 1;
    }

    // ---- dequant + bias into smem staging ----
    CP_WAIT0();
    __syncthreads();
    float* Ct = (float*)smem;                 // [64][132] fp32 = 33792 B
    const int r  = lane >> 2;
    const int cc = (lane & 3) * 2;
#pragma unroll
    for (int i = 0; i < 2; ++i) {
        int row0 = wm + i * 16 + r;
        float sa0 = g_sA[bm + row0];
        float sa1 = g_sA[bm + row0 + 8];
#pragma unroll
        for (int j = 0; j < 4; ++j) {
            int col = wn + j * 8 + cc;
            float sb0 = __uint_as_float(g_sBbits[bn + col])     * (1.0f / 127.0f);
            float sb1 = __uint_as_float(g_sBbits[bn + col + 1]) * (1.0f / 127.0f);
            float b0 = bias[bn + col], b1 = bias[bn + col + 1];
            float v00 = ((float)D1[i][j][0] + (float)D2[i][j][0] * (1.0f / 256.0f)) * sa0 * sb0 + b0;
            float v01 = ((float)D1[i][j][1] + (float)D2[i][j][1] * (1.0f / 256.0f)) * sa0 * sb1 + b1;
            float v10 = ((float)D1[i][j][2] + (float)D2[i][j][2] * (1.0f / 256.0f)) * sa1 * sb0 + b0;
            float v11 = ((float)D1[i][j][3] + (float)D2[i][j][3] * (1.0f / 256.0f)) * sa1 * sb1 + b1;
            Ct[row0 * 132 + col]           = v00;
            Ct[row0 * 132 + col + 1]       = v01;
            Ct[(row0 + 8) * 132 + col]     = v10;
            Ct[(row0 + 8) * 132 + col + 1] = v11;
        }
    }
    __syncthreads();

    // ---- rope / scale / split per head type (4096 pairs, 16 per thread) ----
#pragma unroll 4
    for (int p = 0; p < 16; ++p) {
        int idx = p * 256 + tid;
        int row = idx >> 6;
        int i   = idx & 63;
        int t   = bm + row;
        float x1 = Ct[row * 132 + i];
        float x2 = Ct[row * 132 + i + 64];
        if (head < 20) {
            float ang = (float)pos[t] * g_invfreq[i];
            float c = cosf(ang), s = sinf(ang);
            float y1 = x1 * c - x2 * s;
            float y2 = x2 * c + x1 * s;
            if (head < 16) {
                g_qkv[(size_t)t * NQKV + head * HD + i]      = y1 * SCALE_F;
                g_qkv[(size_t)t * NQKV + head * HD + i + 64] = y2 * SCALE_F;
            } else {
                size_t o = (size_t)t * (NKV * HD) + (head - 16) * HD + i;
                __nv_bfloat16 h1 = __float2bfloat16(y1);
                __nv_bfloat16 h2 = __float2bfloat16(y2);
                g_Khi[o]      = h1;
                g_Khi[o + 64] = h2;
                g_Klo[o]      = __float2bfloat16(y1 - __bfloat162float(h1));
                g_Klo[o + 64] = __float2bfloat16(y2 - __bfloat162float(h2));
            }
        } else {
            size_t o = (size_t)t * (NKV * HD) + (head - 20) * HD + i;
            __nv_bfloat16 h1 = __float2bfloat16(x1);
            __nv_bfloat16 h2 = __float2bfloat16(x2);
            g_Vhi[o]      = h1;
            g_Vhi[o + 64] = h2;
            g_Vlo[o]      = __float2bfloat16(x1 - __bfloat162float(h1));
            g_Vlo[o + 64] = __float2bfloat16(x2 - __bfloat162float(h2));
        }
    }
}

// ---------------------------------------------------------------------------
// Stage 3: attention via mma.sync (R6 2-stage version, unchanged).
// ---------------------------------------------------------------------------
#define APITCH 272
#define ARR_B  (64 * APITCH)
#define ASTAGE (4 * ARR_B)
#define ATTN_SMEM (2 * ASTAGE)

__global__ __launch_bounds__(256, 1)
void attn_mma_kernel(float* __restrict__ out) {
    extern __shared__ char smc[];
    const uint32_t smu = smem_to_u32(smc);
    const int tid  = threadIdx.x;
    const int wid  = tid >> 5;
    const int lane = tid & 31;

    const int qt   = 33 - blockIdx.x;
    const int hp   = blockIdx.y;
    const int head = hp * 2 + (wid >> 2);
    const int kvh  = hp >> 1;
    const int t0   = qt * 64;
    const int mrow = (wid & 3) * 16;

    const int r  = lane >> 2;
    const int cc = (lane & 3) * 2;

    int kts[12];
    int nkt = 0;
    if (t0 >= MMETA && qt >= 10) {
        kts[nkt++] = 0; kts[nkt++] = 1;
        for (int k = qt - 8; k <= qt; ++k) kts[nkt++] = k;
    } else {
        for (int k = 0; k <= qt; ++k) kts[nkt++] = k;
    }

    uint32_t qhi[8][4], qlo[8][4];
    {
        const float* qb = &g_qkv[(size_t)(t0 + mrow) * NQKV + head * HD];
#pragma unroll
        for (int ks = 0; ks < 8; ++ks) {
#pragma unroll
            for (int rg = 0; rg < 4; ++rg) {
                int row = r + (rg & 1) * 8;
                int col = ks * 16 + cc + (rg >> 1) * 8;
                float2 v = *(const float2*)&qb[(size_t)row * NQKV + col];
                uint32_t h = cvt_bf16x2(v.y, v.x);
                float f0 = __uint_as_float(h << 16);
                float f1 = __uint_as_float(h & 0xffff0000u);
                qhi[ks][rg] = h;
                qlo[ks][rg] = cvt_bf16x2(v.y - f1, v.x - f0);
            }
        }
    }

    const __nv_bfloat16* srcKV[4] = { g_Khi, g_Klo, g_Vhi, g_Vlo };
    auto issue = [&](int ti, int buf) {
        int s0 = kts[ti] * 64;
#pragma unroll
        for (int q = 0; q < 16; ++q) {
            int idx = q * 256 + tid;
            int arr = idx >> 10;
            int rem = idx & 1023;
            int row = rem >> 4;
            int ch  = rem & 15;
            const __nv_bfloat16* src = srcKV[arr] + (size_t)(s0 + row) * (NKV * HD) + kvh * HD + ch * 8;
            uint32_t dst = smu + buf * ASTAGE + arr * ARR_B + row * APITCH + ch * 16;
            cp_async16(dst, src);
        }
    };

    const uint32_t koff = (lane & 7) * APITCH + (lane >> 3) * 16;
    const uint32_t voff = ((lane & 7) + ((lane >> 3) & 1) * 8) * APITCH + ((lane >> 3) >> 1) * 16;

    float oacc[16][4];
#pragma unroll
    for (int j = 0; j < 16; ++j)
#pragma unroll
        for (int q = 0; q < 4; ++q) oacc[j][q] = 0.f;
    float m0 = -3.0e38f, m1 = -3.0e38f, l0 = 0.f, l1 = 0.f;

    const int tr0 = t0 + mrow + r;
    const int tr1 = tr0 + 8;

    issue(0, 0); CP_COMMIT();

    for (int it = 0; it < nkt; ++it) {
        if (it + 1 < nkt) issue(it + 1, (it + 1) & 1);
        CP_COMMIT();
        CP_WAIT1();
        __syncthreads();

        const uint32_t kb = smu + (it & 1) * ASTAGE;
        const uint32_t vb = kb + 2 * ARR_B;
        const int s0 = kts[it] * 64;

        float sacc[8][4];
#pragma unroll
        for (int j = 0; j < 8; ++j)
#pragma unroll
            for (int q = 0; q < 4; ++q) sacc[j][q] = 0.f;

#pragma unroll
        for (int j = 0; j < 8; ++j) {
            uint32_t jb = kb + j * (8 * APITCH) + koff;
#pragma unroll
            for (int k2 = 0; k2 < 4; ++k2) {
                uint32_t kh[4], kl[4];
                uint32_t a = jb + k2 * 64;
                ldsm_x4(kh, a);
                ldsm_x4(kl, a + ARR_B);
                mma_bf16(sacc[j], qhi[2 * k2], kh);
                mma_bf16(sacc[j], qhi[2 * k2], kl);
                mma_bf16(sacc[j], qlo[2 * k2], kh);
                mma_bf16(sacc[j], qhi[2 * k2 + 1], kh + 2);
                mma_bf16(sacc[j], qhi[2 * k2 + 1], kl + 2);
                mma_bf16(sacc[j], qlo[2 * k2 + 1], kh + 2);
            }
        }

#pragma unroll
        for (int j = 0; j < 8; ++j) {
            int sb0 = s0 + j * 8 + cc;
#pragma unroll
            for (int cx = 0; cx < 2; ++cx) {
                int s = sb0 + cx;
                bool v0 = (tr0 < MMETA) ? (s <= tr0)
                                        : ((s < MMETA) || ((s <= tr0) && (tr0 - s < WWIN)));
                bool v1 = (tr1 < MMETA) ? (s <= tr1)
                                        : ((s < MMETA) || ((s <= tr1) && (tr1 - s < WWIN)));
                if (!v0) sacc[j][cx]     = NEGV;
                if (!v1) sacc[j][cx + 2] = NEGV;
            }
        }

        float mx0 = NEGV, mx1 = NEGV;
#pragma unroll
        for (int j = 0; j < 8; ++j) {
            mx0 = fmaxf(mx0, fmaxf(sacc[j][0], sacc[j][1]));
            mx1 = fmaxf(mx1, fmaxf(sacc[j][2], sacc[j][3]));
        }
        mx0 = fmaxf(mx0, __shfl_xor_sync(0xffffffffu, mx0, 1));
        mx0 = fmaxf(mx0, __shfl_xor_sync(0xffffffffu, mx0, 2));
        mx1 = fmaxf(mx1, __shfl_xor_sync(0xffffffffu, mx1, 1));
        mx1 = fmaxf(mx1, __shfl_xor_sync(0xffffffffu, mx1, 2));

        float mn0 = fmaxf(m0, mx0);
        float mn1 = fmaxf(m1, mx1);
        float al0 = __expf(m0 - mn0);
        float al1 = __expf(m1 - mn1);
        m0 = mn0; m1 = mn1;

        float sum0 = 0.f, sum1 = 0.f;
#pragma unroll
        for (int j = 0; j < 8; ++j) {
            sacc[j][0] = __expf(sacc[j][0] - m0);
            sacc[j][1] = __expf(sacc[j][1] - m0);
            sacc[j][2] = __expf(sacc[j][2] - m1);
            sacc[j][3] = __expf(sacc[j][3] - m1);
            sum0 += sacc[j][0] + sacc[j][1];
            sum1 += sacc[j][2] + sacc[j][3];
        }
        sum0 += __shfl_xor_sync(0xffffffffu, sum0, 1);
        sum0 += __shfl_xor_sync(0xffffffffu, sum0, 2);
        sum1 += __shfl_xor_sync(0xffffffffu, sum1, 1);
        sum1 += __shfl_xor_sync(0xffffffffu, sum1, 2);
        l0 = l0 * al0 + sum0;
        l1 = l1 * al1 + sum1;

#pragma unroll
        for (int j = 0; j < 16; ++j) {
            oacc[j][0] *= al0; oacc[j][1] *= al0;
            oacc[j][2] *= al1; oacc[j][3] *= al1;
        }

#pragma unroll
        for (int kt = 0; kt < 4; ++kt) {
            uint32_t phi[4], plo[4];
#pragma unroll
            for (int hq = 0; hq < 2; ++hq) {
                const float* sj = sacc[2 * kt + hq];
                uint32_t h0 = cvt_bf16x2(sj[1], sj[0]);
                uint32_t h1 = cvt_bf16x2(sj[3], sj[2]);
                float a0 = __uint_as_float(h0 << 16);
                float a1 = __uint_as_float(h0 & 0xffff0000u);
                float b0 = __uint_as_float(h1 << 16);
                float b1 = __uint_as_float(h1 & 0xffff0000u);
                phi[2 * hq]     = h0;
                phi[2 * hq + 1] = h1;
                plo[2 * hq]     = cvt_bf16x2(sj[1] - a1, sj[0] - a0);
                plo[2 * hq + 1] = cvt_bf16x2(sj[3] - b1, sj[2] - b0);
            }
            uint32_t ktb = vb + kt * (16 * APITCH) + voff;
#pragma unroll
            for (int j2 = 0; j2 < 8; ++j2) {
                uint32_t vh[4], vl[4];
                uint32_t a = ktb + j2 * 32;
                ldsm_x4t(vh, a);
                ldsm_x4t(vl, a + ARR_B);
                mma_bf16(oacc[2 * j2], phi, vh);
                mma_bf16(oacc[2 * j2], phi, vl);
                mma_bf16(oacc[2 * j2], plo, vh);
                mma_bf16(oacc[2 * j2 + 1], phi, vh + 2);
                mma_bf16(oacc[2 * j2 + 1], phi, vl + 2);
                mma_bf16(oacc[2 * j2 + 1], plo, vh + 2);
            }
        }
        __syncthreads();
    }

    float inv0 = 1.0f / l0;
    float inv1 = 1.0f / l1;
    float* ob0 = &out[(size_t)tr0 * (NH * HD) + head * HD + cc];
    float* ob1 = &out[(size_t)tr1 * (NH * HD) + head * HD + cc];
#pragma unroll
    for (int j = 0; j < 16; ++j) {
        float2 v0 = { oacc[j][0] * inv0, oacc[j][1] * inv0 };
        float2 v1 = { oacc[j][2] * inv1, oacc[j][3] * inv1 };
        *(float2*)&ob0[j * 8] = v0;
        *(float2*)&ob1[j * 8] = v1;
    }
}

// ---------------------------------------------------------------------------
extern "C" void kernel_launch(void* const* d_in, const int* in_sizes, int n_in,
                              void* d_out, int out_size) {
    const float* hs   = (const float*)d_in[0];
    const float* w    = (const float*)d_in[1];
    const float* bias = (const float*)d_in[2];
    const int*   pos  = (const int*)d_in[3];
    float* out = (float*)d_out;

    init_invfreq_kernel<<<1, 64>>>();

    quant_a_kernel<<<T_TOK, 256>>>(hs);
    w_colmax_kernel<<<dim3(NQKV / 256, HS / 128), 256>>>(w);
    quant_w_kernel<<<dim3(NQKV / 32, HS / 32), dim3(32, 8)>>>(w);

    cudaFuncSetAttribute(qkv_mma_kernel, cudaFuncAttributeMaxDynamicSharedMemorySize, GEMM_SMEM);
    qkv_mma_kernel<<<dim3(24, T_TOK / 64), 256, GEMM_SMEM>>>(bias, pos);

    cudaFuncSetAttribute(attn_mma_kernel, cudaFuncAttributeMaxDynamicSharedMemorySize, ATTN_SMEM);
    attn_mma_kernel<<<dim3(34, 8), 256, ATTN_SMEM>>>(out);
}

// round 11
// speedup vs baseline: 1.5925x; 1.0731x over previous
#include <cuda_runtime.h>
#include <cuda_bf16.h>
#include <cuda_fp16.h>
#include <cstdint>
#include <math.h>

#define T_TOK 2176
#define HS    2048
#define NQKV  3072
#define NH    16
#define NKV   4
#define HD    128
#define MMETA 128
#define WWIN  512
#define SCALE_F 0.08838834764831845f
#define NEGV  -1.0e30f

// ---------------------------------------------------------------------------
// scratch buffers
// ---------------------------------------------------------------------------
__device__ float g_qkv[T_TOK * NQKV];                    // Q roped+scaled fp32
__device__ int8_t g_A8h[T_TOK * HS];
__device__ int8_t g_A8l[T_TOK * HS];
__device__ int8_t g_W8h[NQKV * HS];                      // W transposed [n][k]
__device__ int8_t g_W8l[NQKV * HS];
__device__ float  g_sA[T_TOK];
__device__ unsigned g_sBbits[NQKV];                      // colmax |W| as float bits

__device__ float  g_Kf[T_TOK * NKV * HD];                // roped K fp32 scratch
__device__ int8_t g_Q8h[T_TOK * NH * HD];
__device__ int8_t g_Q8l[T_TOK * NH * HD];
__device__ float  g_sQ[T_TOK * NH];
__device__ int8_t g_K8h[T_TOK * NKV * HD];
__device__ int8_t g_K8l[T_TOK * NKV * HD];
__device__ float  g_sK[T_TOK * NKV];
__device__ __half g_Vh[T_TOK * NKV * HD];
__device__ __half g_Vl[T_TOK * NKV * HD];
__device__ float g_invfreq[64];

__device__ __forceinline__ uint32_t smem_to_u32(const void* p) {
    uint32_t a;
    asm("{ .reg .u64 t; cvta.to.shared.u64 t, %1; cvt.u32.u64 %0, t; }" : "=r"(a) : "l"(p));
    return a;
}
__device__ __forceinline__ uint32_t cvt_h2(float hi, float lo) {
    uint32_t d;
    asm("cvt.rn.f16x2.f32 %0, %1, %2;" : "=r"(d) : "f"(hi), "f"(lo));
    return d;
}
__device__ __forceinline__ void ldsm_x4(uint32_t* r, uint32_t addr) {
    asm volatile("ldmatrix.sync.aligned.m8n8.x4.shared.b16 {%0,%1,%2,%3}, [%4];"
                 : "=r"(r[0]), "=r"(r[1]), "=r"(r[2]), "=r"(r[3]) : "r"(addr));
}
__device__ __forceinline__ void ldsm_x4t(uint32_t* r, uint32_t addr) {
    asm volatile("ldmatrix.sync.aligned.m8n8.x4.trans.shared.b16 {%0,%1,%2,%3}, [%4];"
                 : "=r"(r[0]), "=r"(r[1]), "=r"(r[2]), "=r"(r[3]) : "r"(addr));
}
__device__ __forceinline__ void mma_s8(int* c, const uint32_t* a, const uint32_t* b) {
    asm volatile(
        "mma.sync.aligned.m16n8k32.row.col.s32.s8.s8.s32 "
        "{%0,%1,%2,%3}, {%4,%5,%6,%7}, {%8,%9}, {%0,%1,%2,%3};"
        : "+r"(c[0]), "+r"(c[1]), "+r"(c[2]), "+r"(c[3])
        : "r"(a[0]), "r"(a[1]), "r"(a[2]), "r"(a[3]), "r"(b[0]), "r"(b[1]));
}
__device__ __forceinline__ void mma_f16(float* c, const uint32_t* a, const uint32_t* b) {
    asm volatile(
        "mma.sync.aligned.m16n8k16.row.col.f32.f16.f16.f32 "
        "{%0,%1,%2,%3}, {%4,%5,%6,%7}, {%8,%9}, {%0,%1,%2,%3};"
        : "+f"(c[0]), "+f"(c[1]), "+f"(c[2]), "+f"(c[3])
        : "r"(a[0]), "r"(a[1]), "r"(a[2]), "r"(a[3]), "r"(b[0]), "r"(b[1]));
}
__device__ __forceinline__ void cp_async16(uint32_t dst, const void* src) {
    asm volatile("cp.async.ca.shared.global [%0], [%1], 16;" :: "r"(dst), "l"(src) : "memory");
}
__device__ __forceinline__ void cp_async4(uint32_t dst, const void* src) {
    asm volatile("cp.async.ca.shared.global [%0], [%1], 4;" :: "r"(dst), "l"(src) : "memory");
}
#define CP_COMMIT() asm volatile("cp.async.commit_group;" ::: "memory")
#define CP_WAIT1()  asm volatile("cp.async.wait_group 1;" ::: "memory")
#define CP_WAIT0()  asm volatile("cp.async.wait_group 0;" ::: "memory")

// ---------------------------------------------------------------------------
__global__ void init_invfreq_kernel() {
    int i = threadIdx.x;
    g_invfreq[i] = (float)exp(-(double)(2 * i) * (1.0 / 128.0) * log(10000.0));
}

// ---------------------------------------------------------------------------
// quantize A: one block per token row; sA = max|a|/127, digits h + l/256
// ---------------------------------------------------------------------------
__global__ void quant_a_kernel(const float* __restrict__ A) {
    const int t = blockIdx.x;
    const int tid = threadIdx.x;
    __shared__ float red[8];
    const float* row = A + (size_t)t * HS;
    float4 v0 = *(const float4*)&row[tid * 8];
    float4 v1 = *(const float4*)&row[tid * 8 + 4];
    float mx = fmaxf(fmaxf(fabsf(v0.x), fabsf(v0.y)), fmaxf(fabsf(v0.z), fabsf(v0.w)));
    mx = fmaxf(mx, fmaxf(fmaxf(fabsf(v1.x), fabsf(v1.y)), fmaxf(fabsf(v1.z), fabsf(v1.w))));
#pragma unroll
    for (int o = 16; o > 0; o >>= 1) mx = fmaxf(mx, __shfl_xor_sync(0xffffffffu, mx, o));
    if ((tid & 31) == 0) red[tid >> 5] = mx;
    __syncthreads();
    float m = fmaxf(fmaxf(fmaxf(red[0], red[1]), fmaxf(red[2], red[3])),
                    fmaxf(fmaxf(red[4], red[5]), fmaxf(red[6], red[7])));
    m = fmaxf(m, 1e-20f);
    if (tid == 0) g_sA[t] = m * (1.0f / 127.0f);
    float inv = 127.0f / m;

    float a[8] = { v0.x, v0.y, v0.z, v0.w, v1.x, v1.y, v1.z, v1.w };
    char hh[8], ll[8];
#pragma unroll
    for (int u = 0; u < 8; ++u) {
        float x = a[u] * inv;
        float h = rintf(x);
        int l = (int)rintf((x - h) * 256.0f);
        if (l > 127) l = 127;
        hh[u] = (char)(int)h;
        ll[u] = (char)l;
    }
    size_t o = (size_t)t * HS + tid * 8;
    *(uint2*)&g_A8h[o] = *(uint2*)hh;
    *(uint2*)&g_A8l[o] = *(uint2*)ll;
}

// ---------------------------------------------------------------------------
// W column max (idempotent atomicMax) then quantize+transpose
// ---------------------------------------------------------------------------
__global__ void w_colmax_kernel(const float* __restrict__ W) {
    int col = blockIdx.x * 256 + threadIdx.x;
    int r0  = blockIdx.y * 128;
    float mx = 0.f;
    for (int r = 0; r < 128; ++r)
        mx = fmaxf(mx, fabsf(W[(size_t)(r0 + r) * NQKV + col]));
    atomicMax(&g_sBbits[col], __float_as_uint(mx));
}

__global__ void quant_w_kernel(const float* __restrict__ W) {
    __shared__ float tile[32][33];
    int n0 = blockIdx.x * 32;
    int k0 = blockIdx.y * 32;
    int tx = threadIdx.x;
    int ty = threadIdx.y;
#pragma unroll
    for (int p = 0; p < 4; ++p) {
        int k = ty + p * 8;
        tile[k][tx] = W[(size_t)(k0 + k) * NQKV + n0 + tx];
    }
    __syncthreads();
#pragma unroll
    for (int p = 0; p < 4; ++p) {
        int n = ty + p * 8;
        float m = fmaxf(__uint_as_float(g_sBbits[n0 + n]), 1e-20f);
        float inv = 127.0f / m;
        float x = tile[tx][n] * inv;
        float h = rintf(x);
        int l = (int)rintf((x - h) * 256.0f);
        if (l > 127) l = 127;
        size_t o = (size_t)(n0 + n) * HS + k0 + tx;
        g_W8h[o] = (int8_t)(int)h;
        g_W8l[o] = (int8_t)l;
    }
}

// ---------------------------------------------------------------------------
// Stage 1: int8 2-digit GEMM (R10).  CTA 64x128, 8 warps (32x32), 3-stage.
// Fused epilogue: bias + RoPE; Q->fp32(scaled), K->fp32 scratch, V->fp16 h/l.
// ---------------------------------------------------------------------------
#define A_T8 4096
#define B_T8 8192
#define STAGE8 24576
#define GEMM_SMEM (3 * STAGE8)

#define SWB(row, chunk) ((row) * 64 + ((((chunk) ^ (((row) >> 1) & 3))) << 4))

__global__ __launch_bounds__(256, 2)
void qkv_mma_kernel(const float* __restrict__ bias, const int* __restrict__ pos) {
    extern __shared__ char smem[];
    const uint32_t sb = smem_to_u32(smem);
    const int tid  = threadIdx.x;
    const int wid  = tid >> 5;
    const int lane = tid & 31;
    const int head = blockIdx.x;
    const int bm = blockIdx.y * 64;
    const int bn = head * 128;
    const int wm = (wid >> 2) * 32;
    const int wn = (wid & 3) * 32;

    const int8_t* srcA[2] = { g_A8h + (size_t)bm * HS, g_A8l + (size_t)bm * HS };
    const int8_t* srcB[2] = { g_W8h + (size_t)bn * HS, g_W8l + (size_t)bn * HS };

    auto issue_stage = [&](int c, int s) {
#pragma unroll
        for (int q = 0; q < 6; ++q) {
            int idx = q * 256 + tid;
            const int8_t* src;
            uint32_t dst;
            if (idx < 512) {
                int arr = idx >> 8;
                int rem = idx & 255;
                int row = rem >> 2, seg = rem & 3;
                src = srcA[arr] + (size_t)row * HS + c * 64 + seg * 16;
                dst = sb + s * STAGE8 + arr * A_T8 + SWB(row, seg);
            } else {
                int arr = (idx - 512) >> 9;
                int rem = idx & 511;
                int row = rem >> 2, seg = rem & 3;
                src = srcB[arr] + (size_t)row * HS + c * 64 + seg * 16;
                dst = sb + s * STAGE8 + 2 * A_T8 + arr * B_T8 + SWB(row, seg);
            }
            cp_async16(dst, src);
        }
    };

    int D1[2][4][4], D2[2][4][4];
#pragma unroll
    for (int i = 0; i < 2; ++i)
#pragma unroll
        for (int j = 0; j < 4; ++j)
#pragma unroll
            for (int q = 0; q < 4; ++q) { D1[i][j][q] = 0; D2[i][j][q] = 0; }

    issue_stage(0, 0); CP_COMMIT();
    issue_stage(1, 1); CP_COMMIT();

    const int arow  = wm + (lane & 15);
    const int ac0   = lane >> 4;
    const int brow4 = (lane & 7) + ((lane >> 4) & 1) * 8;
    const int bc0   = (lane >> 3) & 1;

    const int NCH = HS / 64;   // 32
    int buf = 0;
    for (int c = 0; c < NCH; ++c) {
        CP_WAIT1();
        __syncthreads();

        if (c + 2 < NCH) {
            int nb = buf - 1;
            if (nb < 0) nb = 2;
            issue_stage(c + 2, nb);
        }
        CP_COMMIT();

        const uint32_t base = sb + buf * STAGE8;
#pragma unroll
        for (int ks = 0; ks < 2; ++ks) {
            uint32_t ah[2][4], al[2][4];
#pragma unroll
            for (int i = 0; i < 2; ++i) {
                int row = arow + i * 16;
                uint32_t ad = base + SWB(row, ac0 + ks * 2);
                ldsm_x4(ah[i], ad);
                ldsm_x4(al[i], ad + A_T8);
            }
#pragma unroll
            for (int jp = 0; jp < 2; ++jp) {
                uint32_t bh[4], bl[4];
                int row = wn + jp * 16 + brow4;
                uint32_t bd = base + 2 * A_T8 + SWB(row, bc0 + ks * 2);
                ldsm_x4(bh, bd);
                ldsm_x4(bl, bd + B_T8);
#pragma unroll
                for (int i = 0; i < 2; ++i) {
                    mma_s8(D1[i][2 * jp], ah[i], bh);
                    mma_s8(D2[i][2 * jp], ah[i], bl);
                    mma_s8(D2[i][2 * jp], al[i], bh);
                    mma_s8(D1[i][2 * jp + 1], ah[i], bh + 2);
                    mma_s8(D2[i][2 * jp + 1], ah[i], bl + 2);
                    mma_s8(D2[i][2 * jp + 1], al[i], bh + 2);
                }
            }
        }
        buf = (buf == 2) ? 0 : buf + 1;
    }

    // ---- dequant + bias into smem staging ----
    CP_WAIT0();
    __syncthreads();
    float* Ct = (float*)smem;                 // [64][132]
    const int r  = lane >> 2;
    const int cc = (lane & 3) * 2;
#pragma unroll
    for (int i = 0; i < 2; ++i) {
        int row0 = wm + i * 16 + r;
        float sa0 = g_sA[bm + row0];
        float sa1 = g_sA[bm + row0 + 8];
#pragma unroll
        for (int j = 0; j < 4; ++j) {
            int col = wn + j * 8 + cc;
            float sb0 = __uint_as_float(g_sBbits[bn + col])     * (1.0f / 127.0f);
            float sb1 = __uint_as_float(g_sBbits[bn + col + 1]) * (1.0f / 127.0f);
            float b0 = bias[bn + col], b1 = bias[bn + col + 1];
            Ct[row0 * 132 + col]           = ((float)D1[i][j][0] + (float)D2[i][j][0] * (1.0f / 256.0f)) * sa0 * sb0 + b0;
            Ct[row0 * 132 + col + 1]       = ((float)D1[i][j][1] + (float)D2[i][j][1] * (1.0f / 256.0f)) * sa0 * sb1 + b1;
            Ct[(row0 + 8) * 132 + col]     = ((float)D1[i][j][2] + (float)D2[i][j][2] * (1.0f / 256.0f)) * sa1 * sb0 + b0;
            Ct[(row0 + 8) * 132 + col + 1] = ((float)D1[i][j][3] + (float)D2[i][j][3] * (1.0f / 256.0f)) * sa1 * sb1 + b1;
        }
    }
    __syncthreads();

    // ---- rope / store per head type ----
#pragma unroll 4
    for (int p = 0; p < 16; ++p) {
        int idx = p * 256 + tid;
        int row = idx >> 6;
        int i   = idx & 63;
        int t   = bm + row;
        float x1 = Ct[row * 132 + i];
        float x2 = Ct[row * 132 + i + 64];
        if (head < 20) {
            float ang = (float)pos[t] * g_invfreq[i];
            float c = cosf(ang), s = sinf(ang);
            float y1 = x1 * c - x2 * s;
            float y2 = x2 * c + x1 * s;
            if (head < 16) {
                g_qkv[(size_t)t * NQKV + head * HD + i]      = y1 * SCALE_F;
                g_qkv[(size_t)t * NQKV + head * HD + i + 64] = y2 * SCALE_F;
            } else {
                size_t o = (size_t)t * (NKV * HD) + (head - 16) * HD + i;
                g_Kf[o]      = y1;
                g_Kf[o + 64] = y2;
            }
        } else {
            size_t o = (size_t)t * (NKV * HD) + (head - 20) * HD + i;
            __half h1 = __float2half_rn(x1);
            __half h2 = __float2half_rn(x2);
            g_Vh[o]      = h1;
            g_Vh[o + 64] = h2;
            g_Vl[o]      = __float2half_rn(x1 - __half2float(h1));
            g_Vl[o + 64] = __float2half_rn(x2 - __half2float(h2));
        }
    }
}

// ---------------------------------------------------------------------------
// Stage 2: quantize Q (per t,head) and K (per t,kvh) to int8 2-digit.
// One block per token.
// ---------------------------------------------------------------------------
__global__ void quant_qk_kernel() {
    const int t = blockIdx.x;
    const int tid = threadIdx.x;

    // Q: 2048 values, 8 per thread; head = tid>>4; 16-thread group reduce
    {
        const float* qr = g_qkv + (size_t)t * NQKV + tid * 8;
        float a[8];
        *(float4*)&a[0] = *(const float4*)&qr[0];
        *(float4*)&a[4] = *(const float4*)&qr[4];
        float mx = 0.f;
#pragma unroll
        for (int u = 0; u < 8; ++u) mx = fmaxf(mx, fabsf(a[u]));
#pragma unroll
        for (int o = 8; o > 0; o >>= 1) mx = fmaxf(mx, __shfl_xor_sync(0xffffffffu, mx, o));
        float m = fmaxf(mx, 1e-20f);
        int h = tid >> 4;
        if ((tid & 15) == 0) g_sQ[(size_t)t * NH + h] = m * (1.0f / 127.0f);
        float inv = 127.0f / m;
        char hh[8], ll[8];
#pragma unroll
        for (int u = 0; u < 8; ++u) {
            float x = a[u] * inv;
            float hq = rintf(x);
            int l = (int)rintf((x - hq) * 256.0f);
            if (l > 127) l = 127;
            hh[u] = (char)(int)hq;
            ll[u] = (char)l;
        }
        size_t o = (size_t)t * (NH * HD) + tid * 8;
        *(uint2*)&g_Q8h[o] = *(uint2*)hh;
        *(uint2*)&g_Q8l[o] = *(uint2*)ll;
    }

    // K: 512 values, threads 0..63, kvh = tid>>4
    if (tid < 64) {
        const float* kr = g_Kf + (size_t)t * (NKV * HD) + tid * 8;
        float a[8];
        *(float4*)&a[0] = *(const float4*)&kr[0];
        *(float4*)&a[4] = *(const float4*)&kr[4];
        float mx = 0.f;
#pragma unroll
        for (int u = 0; u < 8; ++u) mx = fmaxf(mx, fabsf(a[u]));
#pragma unroll
        for (int o = 8; o > 0; o >>= 1) mx = fmaxf(mx, __shfl_xor_sync(0xffffffffu, mx, o));
        float m = fmaxf(mx, 1e-20f);
        int kvh = tid >> 4;
        if ((tid & 15) == 0) g_sK[(size_t)t * NKV + kvh] = m * (1.0f / 127.0f);
        float inv = 127.0f / m;
        char hh[8], ll[8];
#pragma unroll
        for (int u = 0; u < 8; ++u) {
            float x = a[u] * inv;
            float hq = rintf(x);
            int l = (int)rintf((x - hq) * 256.0f);
            if (l > 127) l = 127;
            hh[u] = (char)(int)hq;
            ll[u] = (char)l;
        }
        size_t o = (size_t)t * (NKV * HD) + tid * 8;
        *(uint2*)&g_K8h[o] = *(uint2*)hh;
        *(uint2*)&g_K8l[o] = *(uint2*)ll;
    }
}

// ---------------------------------------------------------------------------
// Stage 3: attention.  QK^T int8 2-digit, PV fp16 (V split h/l).
// 2 heads/CTA (warps 0-3 / 4-7), 2-stage cp.async KV, Q staged once.
// ---------------------------------------------------------------------------
#define K8_B 8192
#define V_B  17408
#define ASTG (2 * K8_B + 2 * V_B + 256)   // 51456
#define Q_TOTAL 32768
#define ATTN_SMEM (Q_TOTAL + 2 * ASTG)    // 135680

#define SWQ(row, chunk) ((row) * 128 + ((((chunk) ^ ((row) & 7))) << 4))

__global__ __launch_bounds__(256, 1)
void attn_mma_kernel(float* __restrict__ out) {
    extern __shared__ char smc[];
    const uint32_t smu = smem_to_u32(smc);
    const int tid  = threadIdx.x;
    const int wid  = tid >> 5;
    const int lane = tid & 31;

    const int qt   = 33 - blockIdx.x;
    const int hp   = blockIdx.y;
    const int head = hp * 2 + (wid >> 2);
    const int kvh  = hp >> 1;
    const int t0   = qt * 64;
    const int mrow = (wid & 3) * 16;

    const int r  = lane >> 2;
    const int cc = (lane & 3) * 2;

    int kts[12];
    int nkt = 0;
    if (t0 >= MMETA && qt >= 10) {
        kts[nkt++] = 0; kts[nkt++] = 1;
        for (int k = qt - 8; k <= qt; ++k) kts[nkt++] = k;
    } else {
        for (int k = 0; k <= qt; ++k) kts[nkt++] = k;
    }

    // ---- stage Q8 tiles (2 heads x 2 digits), part of first cp.async group ----
#pragma unroll
    for (int q = 0; q < 8; ++q) {
        int idx = q * 256 + tid;
        int hd  = idx >> 10;
        int rem = idx & 1023;
        int dg  = rem >> 9;
        int r2  = rem & 511;
        int row = r2 >> 3;
        int seg = r2 & 7;
        const int8_t* src = (dg ? g_Q8l : g_Q8h) +
                            (size_t)(t0 + row) * (NH * HD) + (hp * 2 + hd) * HD + seg * 16;
        cp_async16(smu + hd * 16384 + dg * 8192 + SWQ(row, seg), src);
    }

    auto issue = [&](int ti, int buf) {
        int s0 = kts[ti] * 64;
        uint32_t base = smu + Q_TOTAL + buf * ASTG;
#pragma unroll
        for (int q = 0; q < 12; ++q) {
            int idx = q * 256 + tid;
            if (idx < 1024) {
                int dg = idx >> 9, rem = idx & 511, row = rem >> 3, seg = rem & 7;
                const int8_t* src = (dg ? g_K8l : g_K8h) +
                                    (size_t)(s0 + row) * (NKV * HD) + kvh * HD + seg * 16;
                cp_async16(base + dg * K8_B + SWQ(row, seg), src);
            } else {
                int v = idx - 1024, dg = v >> 10, rem = v & 1023, row = rem >> 4, ch = rem & 15;
                const __half* src = (dg ? g_Vl : g_Vh) +
                                    (size_t)(s0 + row) * (NKV * HD) + kvh * HD + ch * 8;
                cp_async16(base + 2 * K8_B + dg * V_B + row * 272 + ch * 16, src);
            }
        }
        if (tid < 64)
            cp_async4(base + 2 * K8_B + 2 * V_B + tid * 4, &g_sK[(size_t)(s0 + tid) * NKV + kvh]);
    };

    const int tr0 = t0 + mrow + r;
    const int tr1 = tr0 + 8;
    const float sq0 = g_sQ[(size_t)tr0 * NH + head];
    const float sq1 = g_sQ[(size_t)tr1 * NH + head];

    const int brow4 = (lane & 7) + ((lane >> 4) & 1) * 8;
    const int bc0   = (lane >> 3) & 1;
    const uint32_t voff = ((lane & 7) + ((lane >> 3) & 1) * 8) * 272 + ((lane >> 3) >> 1) * 16;

    float oacc[16][4];
#pragma unroll
    for (int j = 0; j < 16; ++j)
#pragma unroll
        for (int q = 0; q < 4; ++q) oacc[j][q] = 0.f;
    float m0 = -3.0e38f, m1 = -3.0e38f, l0 = 0.f, l1 = 0.f;

    uint32_t qh[4][4], ql[4][4];

    issue(0, 0); CP_COMMIT();

    for (int it = 0; it < nkt; ++it) {
        if (it + 1 < nkt) issue(it + 1, (it + 1) & 1);
        CP_COMMIT();
        CP_WAIT1();
        __syncthreads();

        const uint32_t base = smu + Q_TOTAL + (it & 1) * ASTG;
        const float* sKs = (const float*)(smc + Q_TOTAL + (it & 1) * ASTG + 2 * K8_B + 2 * V_B);
        const int s0 = kts[it] * 64;

        if (it == 0) {
            uint32_t qb = smu + (wid >> 2) * 16384;
#pragma unroll
            for (int kc = 0; kc < 4; ++kc) {
                uint32_t ad = qb + SWQ(mrow + (lane & 15), kc * 2 + (lane >> 4));
                ldsm_x4(qh[kc], ad);
                ldsm_x4(ql[kc], ad + 8192);
            }
        }

        // ---- S = Q K^T (int8 2-digit) ----
        int S1[8][4], S2[8][4];
#pragma unroll
        for (int j = 0; j < 8; ++j)
#pragma unroll
            for (int q = 0; q < 4; ++q) { S1[j][q] = 0; S2[j][q] = 0; }

#pragma unroll
        for (int j = 0; j < 4; ++j) {
#pragma unroll
            for (int kc = 0; kc < 4; ++kc) {
                uint32_t kh[4], kl[4];
                uint32_t bd = base + SWQ(j * 16 + brow4, kc * 2 + bc0);
                ldsm_x4(kh, bd);
                ldsm_x4(kl, bd + K8_B);
                mma_s8(S1[2 * j], qh[kc], kh);
                mma_s8(S2[2 * j], qh[kc], kl);
                mma_s8(S2[2 * j], ql[kc], kh);
                mma_s8(S1[2 * j + 1], qh[kc], kh + 2);
                mma_s8(S2[2 * j + 1], qh[kc], kl + 2);
                mma_s8(S2[2 * j + 1], ql[kc], kh + 2);
            }
        }

        // ---- dequant + mask ----
        float sacc[8][4];
#pragma unroll
        for (int j = 0; j < 8; ++j) {
            int c0 = j * 8 + cc;
            float k0s = sKs[c0], k1s = sKs[c0 + 1];
            sacc[j][0] = ((float)S1[j][0] + (float)S2[j][0] * (1.0f / 256.0f)) * (sq0 * k0s);
            sacc[j][1] = ((float)S1[j][1] + (float)S2[j][1] * (1.0f / 256.0f)) * (sq0 * k1s);
            sacc[j][2] = ((float)S1[j][2] + (float)S2[j][2] * (1.0f / 256.0f)) * (sq1 * k0s);
            sacc[j][3] = ((float)S1[j][3] + (float)S2[j][3] * (1.0f / 256.0f)) * (sq1 * k1s);
        }

#pragma unroll
        for (int j = 0; j < 8; ++j) {
            int sb0 = s0 + j * 8 + cc;
#pragma unroll
            for (int cx = 0; cx < 2; ++cx) {
                int s = sb0 + cx;
                bool v0 = (tr0 < MMETA) ? (s <= tr0)
                                        : ((s < MMETA) || ((s <= tr0) && (tr0 - s < WWIN)));
                bool v1 = (tr1 < MMETA) ? (s <= tr1)
                                        : ((s < MMETA) || ((s <= tr1) && (tr1 - s < WWIN)));
                if (!v0) sacc[j][cx]     = NEGV;
                if (!v1) sacc[j][cx + 2] = NEGV;
            }
        }

        // ---- online softmax (fp16 P, sums from rounded values) ----
        float mx0 = NEGV, mx1 = NEGV;
#pragma unroll
        for (int j = 0; j < 8; ++j) {
            mx0 = fmaxf(mx0, fmaxf(sacc[j][0], sacc[j][1]));
            mx1 = fmaxf(mx1, fmaxf(sacc[j][2], sacc[j][3]));
        }
        mx0 = fmaxf(mx0, __shfl_xor_sync(0xffffffffu, mx0, 1));
        mx0 = fmaxf(mx0, __shfl_xor_sync(0xffffffffu, mx0, 2));
        mx1 = fmaxf(mx1, __shfl_xor_sync(0xffffffffu, mx1, 1));
        mx1 = fmaxf(mx1, __shfl_xor_sync(0xffffffffu, mx1, 2));

        float mn0 = fmaxf(m0, mx0);
        float mn1 = fmaxf(m1, mx1);
        float al0 = __expf(m0 - mn0);
        float al1 = __expf(m1 - mn1);
        m0 = mn0; m1 = mn1;

        uint32_t pp[8][2];
        float sum0 = 0.f, sum1 = 0.f;
#pragma unroll
        for (int j = 0; j < 8; ++j) {
            float p0 = __expf(sacc[j][0] - m0);
            float p1 = __expf(sacc[j][1] - m0);
            float p2 = __expf(sacc[j][2] - m1);
            float p3 = __expf(sacc[j][3] - m1);
            uint32_t h0 = cvt_h2(p1, p0);
            uint32_t h1 = cvt_h2(p3, p2);
            pp[j][0] = h0;
            pp[j][1] = h1;
            float2 f0 = __half22float2(*reinterpret_cast<__half2*>(&h0));
            float2 f1 = __half22float2(*reinterpret_cast<__half2*>(&h1));
            sum0 += f0.x + f0.y;
            sum1 += f1.x + f1.y;
        }
        sum0 += __shfl_xor_sync(0xffffffffu, sum0, 1);
        sum0 += __shfl_xor_sync(0xffffffffu, sum0, 2);
        sum1 += __shfl_xor_sync(0xffffffffu, sum1, 1);
        sum1 += __shfl_xor_sync(0xffffffffu, sum1, 2);
        l0 = l0 * al0 + sum0;
        l1 = l1 * al1 + sum1;

#pragma unroll
        for (int j = 0; j < 16; ++j) {
            oacc[j][0] *= al0; oacc[j][1] *= al0;
            oacc[j][2] *= al1; oacc[j][3] *= al1;
        }

        // ---- O += P V (fp16; V split h/l) ----
        const uint32_t vbase = base + 2 * K8_B;
#pragma unroll
        for (int kt = 0; kt < 4; ++kt) {
            uint32_t phi[4] = { pp[2 * kt][0], pp[2 * kt][1], pp[2 * kt + 1][0], pp[2 * kt + 1][1] };
            uint32_t ktb = vbase + kt * (16 * 272) + voff;
#pragma unroll
            for (int j2 = 0; j2 < 8; ++j2) {
                uint32_t vh[4], vl[4];
                uint32_t a = ktb + j2 * 32;
                ldsm_x4t(vh, a);
                ldsm_x4t(vl, a + V_B);
                mma_f16(oacc[2 * j2], phi, vh);
                mma_f16(oacc[2 * j2], phi, vl);
                mma_f16(oacc[2 * j2 + 1], phi, vh + 2);
                mma_f16(oacc[2 * j2 + 1], phi, vl + 2);
            }
        }
        __syncthreads();
    }

    float inv0 = 1.0f / l0;
    float inv1 = 1.0f / l1;
    float* ob0 = &out[(size_t)tr0 * (NH * HD) + head * HD + cc];
    float* ob1 = &out[(size_t)tr1 * (NH * HD) + head * HD + cc];
#pragma unroll
    for (int j = 0; j < 16; ++j) {
        float2 v0 = { oacc[j][0] * inv0, oacc[j][1] * inv0 };
        float2 v1 = { oacc[j][2] * inv1, oacc[j][3] * inv1 };
        *(float2*)&ob0[j * 8] = v0;
        *(float2*)&ob1[j * 8] = v1;
    }
}

// ---------------------------------------------------------------------------
extern "C" void kernel_launch(void* const* d_in, const int* in_sizes, int n_in,
                              void* d_out, int out_size) {
    const float* hs   = (const float*)d_in[0];
    const float* w    = (const float*)d_in[1];
    const float* bias = (const float*)d_in[2];
    const int*   pos  = (const int*)d_in[3];
    float* out = (float*)d_out;

    init_invfreq_kernel<<<1, 64>>>();

    quant_a_kernel<<<T_TOK, 256>>>(hs);
    w_colmax_kernel<<<dim3(NQKV / 256, HS / 128), 256>>>(w);
    quant_w_kernel<<<dim3(NQKV / 32, HS / 32), dim3(32, 8)>>>(w);

    cudaFuncSetAttribute(qkv_mma_kernel, cudaFuncAttributeMaxDynamicSharedMemorySize, GEMM_SMEM);
    qkv_mma_kernel<<<dim3(24, T_TOK / 64), 256, GEMM_SMEM>>>(bias, pos);

    quant_qk_kernel<<<T_TOK, 256>>>();

    cudaFuncSetAttribute(attn_mma_kernel, cudaFuncAttributeMaxDynamicSharedMemorySize, ATTN_SMEM);
    attn_mma_kernel<<<dim3(34, 8), 256, ATTN_SMEM>>>(out);
}